// round 1
// baseline (speedup 1.0000x reference)
#include <cuda_runtime.h>

// Problem constants (fixed by the dataset)
#define B_   4
#define T_   2048
#define C_   1024
#define H_   16
#define HD_  64
#define M_   (B_ * T_)          // 8192 rows
#define C3_  (3 * C_)           // 3072

// Scratch (device globals: allocation-free per harness rules)
__device__ float g_qkv[(size_t)M_ * C3_];   // [M, 3C]  q|k|v packed per row
__device__ float g_y[(size_t)M_ * C_];      // [M, C]   attention output pre-proj

// ---------------------------------------------------------------------------
// SGEMM:  Cout[M,N] = A[M,K] @ W[N,K]^T + bias[N]
// 128x128 block tile, BK=16, 256 threads, 8x8 micro-tile (quadrant split).
// ---------------------------------------------------------------------------
__global__ __launch_bounds__(256) void sgemm_bias(
    const float* __restrict__ A, const float* __restrict__ W,
    const float* __restrict__ bias, float* __restrict__ Cout,
    int M, int N, int K)
{
    __shared__ float As[16][132];   // [k][m], padded
    __shared__ float Bs[16][132];   // [k][n], padded

    const int bm = blockIdx.y * 128;
    const int bn = blockIdx.x * 128;
    const int tid = threadIdx.x;
    const int tx = tid & 15;        // 0..15 -> n
    const int ty = tid >> 4;        // 0..15 -> m

    float acc[8][8];
    #pragma unroll
    for (int i = 0; i < 8; i++)
        #pragma unroll
        for (int j = 0; j < 8; j++) acc[i][j] = 0.f;

    for (int k0 = 0; k0 < K; k0 += 16) {
        // Load 128x16 A tile and 128x16 W tile (transposed into smem).
        #pragma unroll
        for (int t = 0; t < 2; t++) {
            int idx = tid + t * 256;          // 0..511 float4 slots
            int r = idx >> 2;                 // 0..127
            int c = (idx & 3) << 2;           // 0,4,8,12
            float4 av = *(const float4*)(A + (size_t)(bm + r) * K + k0 + c);
            As[c + 0][r] = av.x; As[c + 1][r] = av.y;
            As[c + 2][r] = av.z; As[c + 3][r] = av.w;
            float4 wv = *(const float4*)(W + (size_t)(bn + r) * K + k0 + c);
            Bs[c + 0][r] = wv.x; Bs[c + 1][r] = wv.y;
            Bs[c + 2][r] = wv.z; Bs[c + 3][r] = wv.w;
        }
        __syncthreads();

        #pragma unroll
        for (int kk = 0; kk < 16; kk++) {
            float4 a0 = *(const float4*)&As[kk][ty * 4];
            float4 a1 = *(const float4*)&As[kk][64 + ty * 4];
            float4 b0 = *(const float4*)&Bs[kk][tx * 4];
            float4 b1 = *(const float4*)&Bs[kk][64 + tx * 4];
            float a[8] = {a0.x, a0.y, a0.z, a0.w, a1.x, a1.y, a1.z, a1.w};
            float b[8] = {b0.x, b0.y, b0.z, b0.w, b1.x, b1.y, b1.z, b1.w};
            #pragma unroll
            for (int i = 0; i < 8; i++)
                #pragma unroll
                for (int j = 0; j < 8; j++)
                    acc[i][j] += a[i] * b[j];
        }
        __syncthreads();
    }

    #pragma unroll
    for (int i = 0; i < 8; i++) {
        int row = bm + ((i < 4) ? (ty * 4 + i) : (64 + ty * 4 + i - 4));
        #pragma unroll
        for (int q = 0; q < 2; q++) {
            int col = bn + q * 64 + tx * 4;
            float4 r;
            r.x = acc[i][q * 4 + 0] + bias[col + 0];
            r.y = acc[i][q * 4 + 1] + bias[col + 1];
            r.z = acc[i][q * 4 + 2] + bias[col + 2];
            r.w = acc[i][q * 4 + 3] + bias[col + 3];
            *(float4*)(Cout + (size_t)row * N + col) = r;
        }
    }
}

// ---------------------------------------------------------------------------
// Flash attention (fp32, online softmax).
// grid = (T/64, H, B), 256 threads; 64 q-rows x 64 head-dim per block.
// Thread (tx,ty) owns S/O micro-tile rows 4*ty+i, cols 4*tx+j.
// ---------------------------------------------------------------------------
#define ATTN_SMEM (4 * 64 * 65 * 4 + 64 * 4)

__global__ __launch_bounds__(256) void flash_attn(
    const float* __restrict__ qkv, const int* __restrict__ amask,
    float* __restrict__ y)
{
    extern __shared__ float sm[];
    float* Qs = sm;                  // [64][65]
    float* Ks = Qs + 64 * 65;        // [64][65]
    float* Vs = Ks + 64 * 65;        // [64][65]
    float* Ps = Vs + 64 * 65;        // [64][65]
    int*   smask = (int*)(Ps + 64 * 65);   // [64]

    const int b = blockIdx.z, h = blockIdx.y, qt = blockIdx.x;
    const int q0 = qt * 64;
    const int tid = threadIdx.x;
    const int tx = tid & 15, ty = tid >> 4;
    const float* base = qkv + (size_t)b * T_ * C3_ + h * HD_;

    // Load Q tile (64 rows x 64 floats)
    #pragma unroll
    for (int t = 0; t < 4; t++) {
        int idx = tid + t * 256;     // 0..1023 float4 slots
        int r = idx >> 4;            // 0..63
        int c = (idx & 15) << 2;     // 0..60
        float4 v = *(const float4*)(base + (size_t)(q0 + r) * C3_ + c);
        Qs[r * 65 + c + 0] = v.x; Qs[r * 65 + c + 1] = v.y;
        Qs[r * 65 + c + 2] = v.z; Qs[r * 65 + c + 3] = v.w;
    }

    float m_i[4], l_i[4], o[4][4];
    #pragma unroll
    for (int i = 0; i < 4; i++) {
        m_i[i] = -1e30f; l_i[i] = 0.f;
        #pragma unroll
        for (int j = 0; j < 4; j++) o[i][j] = 0.f;
    }

    for (int kt = 0; kt <= qt; kt++) {
        const int k0 = kt * 64;
        __syncthreads();   // previous iteration's Ks/Vs/Ps reads complete
        if (tid < 64) smask[tid] = amask[b * T_ + k0 + tid];
        #pragma unroll
        for (int t = 0; t < 4; t++) {
            int idx = tid + t * 256;
            int r = idx >> 4;
            int c = (idx & 15) << 2;
            float4 kv = *(const float4*)(base + C_  + (size_t)(k0 + r) * C3_ + c);
            Ks[r * 65 + c + 0] = kv.x; Ks[r * 65 + c + 1] = kv.y;
            Ks[r * 65 + c + 2] = kv.z; Ks[r * 65 + c + 3] = kv.w;
            float4 vv = *(const float4*)(base + 2 * C_ + (size_t)(k0 + r) * C3_ + c);
            Vs[r * 65 + c + 0] = vv.x; Vs[r * 65 + c + 1] = vv.y;
            Vs[r * 65 + c + 2] = vv.z; Vs[r * 65 + c + 3] = vv.w;
        }
        __syncthreads();
        // left-aligned mask: first key of tile invalid => all remaining invalid
        if (smask[0] == 0) break;

        // S = Q @ K^T
        float s[4][4];
        #pragma unroll
        for (int i = 0; i < 4; i++)
            #pragma unroll
            for (int j = 0; j < 4; j++) s[i][j] = 0.f;
        #pragma unroll 8
        for (int d = 0; d < 64; d++) {
            float qv[4], kv[4];
            #pragma unroll
            for (int i = 0; i < 4; i++) qv[i] = Qs[(ty * 4 + i) * 65 + d];
            #pragma unroll
            for (int j = 0; j < 4; j++) kv[j] = Ks[(tx * 4 + j) * 65 + d];
            #pragma unroll
            for (int i = 0; i < 4; i++)
                #pragma unroll
                for (int j = 0; j < 4; j++)
                    s[i][j] += qv[i] * kv[j];
        }

        // mask + scale + online softmax
        #pragma unroll
        for (int i = 0; i < 4; i++) {
            const int qr = q0 + ty * 4 + i;
            float tm = -1e30f;
            #pragma unroll
            for (int j = 0; j < 4; j++) {
                int kc = k0 + tx * 4 + j;
                float v = (kc <= qr && smask[tx * 4 + j]) ? s[i][j] * 0.125f : -1e30f;
                s[i][j] = v;
                tm = fmaxf(tm, v);
            }
            #pragma unroll
            for (int off = 8; off; off >>= 1)
                tm = fmaxf(tm, __shfl_xor_sync(0xffffffffu, tm, off, 16));
            float mn = fmaxf(m_i[i], tm);
            float corr = __expf(m_i[i] - mn);
            float rs = 0.f;
            #pragma unroll
            for (int j = 0; j < 4; j++) {
                float p = __expf(s[i][j] - mn);
                s[i][j] = p;
                rs += p;
            }
            #pragma unroll
            for (int off = 8; off; off >>= 1)
                rs += __shfl_xor_sync(0xffffffffu, rs, off, 16);
            l_i[i] = l_i[i] * corr + rs;
            m_i[i] = mn;
            #pragma unroll
            for (int j = 0; j < 4; j++) {
                o[i][j] *= corr;
                Ps[(ty * 4 + i) * 65 + tx * 4 + j] = s[i][j];
            }
        }
        __syncthreads();

        // O += P @ V
        #pragma unroll 8
        for (int kk = 0; kk < 64; kk++) {
            float pv[4], vv[4];
            #pragma unroll
            for (int i = 0; i < 4; i++) pv[i] = Ps[(ty * 4 + i) * 65 + kk];
            #pragma unroll
            for (int j = 0; j < 4; j++) vv[j] = Vs[kk * 65 + tx * 4 + j];
            #pragma unroll
            for (int i = 0; i < 4; i++)
                #pragma unroll
                for (int j = 0; j < 4; j++)
                    o[i][j] += pv[i] * vv[j];
        }
    }

    // write y (query-mask applied => invalid rows zero)
    #pragma unroll
    for (int i = 0; i < 4; i++) {
        int qr = q0 + ty * 4 + i;
        int qm = amask[b * T_ + qr];
        float inv = (qm && l_i[i] > 0.f) ? (1.f / l_i[i]) : 0.f;
        size_t off = ((size_t)b * T_ + qr) * C_ + h * HD_ + tx * 4;
        #pragma unroll
        for (int j = 0; j < 4; j++) y[off + j] = o[i][j] * inv;
    }
}

// ---------------------------------------------------------------------------
extern "C" void kernel_launch(void* const* d_in, const int* in_sizes, int n_in,
                              void* d_out, int out_size)
{
    const float* x    = (const float*)d_in[0];
    const int*   am   = (const int*)  d_in[1];
    const float* Wqkv = (const float*)d_in[2];
    const float* bqkv = (const float*)d_in[3];
    const float* Wo   = (const float*)d_in[4];
    const float* bo   = (const float*)d_in[5];
    float* out = (float*)d_out;

    float *qkv, *yb;
    cudaGetSymbolAddress((void**)&qkv, g_qkv);
    cudaGetSymbolAddress((void**)&yb,  g_y);

    cudaFuncSetAttribute(flash_attn, cudaFuncAttributeMaxDynamicSharedMemorySize,
                         ATTN_SMEM);

    sgemm_bias<<<dim3(C3_ / 128, M_ / 128), 256>>>(x, Wqkv, bqkv, qkv, M_, C3_, C_);
    flash_attn<<<dim3(T_ / 64, H_, B_), 256, ATTN_SMEM>>>(qkv, am, yb);
    sgemm_bias<<<dim3(C_ / 128, M_ / 128), 256>>>(yb, Wo, bo, out, M_, C_, C_);
}

// round 3
// speedup vs baseline: 1.3514x; 1.3514x over previous
#include <cuda_runtime.h>
#include <cuda_bf16.h>
#include <cstdint>

// Problem constants
#define B_   4
#define T_   2048
#define C_   1024
#define H_   16
#define HD_  64
#define M_   (B_ * T_)          // 8192
#define C3_  (3 * C_)           // 3072
#define KP_  (3 * C_)           // 3072 concat-K (hi|lo|hi)

// Does this device pass support full tcgen05 (arch-specific 'a' features)?
#if !defined(__CUDA_ARCH__) || defined(__CUDA_ARCH_FEAT_SM103_ALL)
#define TC_OK 1
#else
#define TC_OK 0
#endif

// ---------------------------------------------------------------------------
// Scratch (device globals: allocation-free per harness rules)
// ---------------------------------------------------------------------------
__device__ float g_qkv[(size_t)M_ * C3_];                   // fp32 q|k|v
__device__ __nv_bfloat16 g_xs [(size_t)M_  * KP_];          // x  split [h|l|h]
__device__ __nv_bfloat16 g_wqs[(size_t)C3_ * KP_];          // Wqkv split [h|h|l]
__device__ __nv_bfloat16 g_wos[(size_t)C_  * KP_];          // Wo   split [h|h|l]
__device__ __nv_bfloat16 g_ys [(size_t)M_  * KP_];          // y  split [h|l|h]

// ---------------------------------------------------------------------------
// Common helpers
// ---------------------------------------------------------------------------
__device__ __forceinline__ uint32_t smem_u32(const void* p) {
    uint32_t a;
    asm("{ .reg .u64 t; cvta.to.shared.u64 t, %1; cvt.u32.u64 %0, t; }"
        : "=r"(a) : "l"(p));
    return a;
}

#if TC_OK
__device__ __forceinline__ uint32_t elect_one() {
    uint32_t p;
    asm volatile("{ .reg .pred p; elect.sync _|p, 0xFFFFFFFF; selp.b32 %0, 1, 0, p; }"
                 : "=r"(p));
    return p;
}
#define TC_ALLOC(smem_addr, n)  asm volatile("tcgen05.alloc.cta_group::1.sync.aligned.shared::cta.b32 [%0], %1;" :: "r"(smem_addr), "r"(n) : "memory")
#define TC_DEALLOC(tmem, n)     asm volatile("tcgen05.dealloc.cta_group::1.sync.aligned.b32 %0, %1;" :: "r"(tmem), "r"(n))
#define TC_COMMIT(mbar)         asm volatile("tcgen05.commit.cta_group::1.mbarrier::arrive::one.shared::cluster.b64 [%0];" :: "r"(mbar) : "memory")
#define TC_FENCE_AFTER()        asm volatile("tcgen05.fence::after_thread_sync;" ::: "memory")
#define TC_FENCE_BEFORE()       asm volatile("tcgen05.fence::before_thread_sync;" ::: "memory")
#define TC_WAIT_LD()            asm volatile("tcgen05.wait::ld.sync.aligned;" ::: "memory")
#define MBAR_INIT(mbar, cnt)    asm volatile("mbarrier.init.shared.b64 [%0], %1;" :: "r"(mbar), "r"(cnt) : "memory")
#define FENCE_ASYNC_SHARED()    asm volatile("fence.proxy.async.shared::cta;" ::: "memory")

#define MBAR_WAIT(mbar, parity) do {                                          \
    uint32_t _m = (mbar), _p = (parity), _d;                                  \
    asm volatile("{ .reg .pred p; mbarrier.try_wait.parity.acquire.cta.shared::cta.b64 p, [%1], %2; selp.b32 %0, 1, 0, p; }" \
                 : "=r"(_d) : "r"(_m), "r"(_p) : "memory");                   \
    if (!_d) {                                                                \
        asm volatile("{ .reg .pred P1; WL_%=:\n\t"                            \
            "mbarrier.try_wait.parity.acquire.cta.shared::cta.b64 P1, [%0], %1, 0x989680;\n\t" \
            "@P1 bra.uni WD_%=; bra.uni WL_%=; WD_%=: }"                      \
            :: "r"(_m), "r"(_p) : "memory");                                  \
    }                                                                          \
} while (0)

__device__ __forceinline__ void tc_mma_f16_ss(
    uint32_t d_tmem, uint64_t a_desc, uint64_t b_desc, uint32_t idesc, uint32_t en)
{
    asm volatile(
        "{ .reg .pred p; setp.ne.u32 p, %5, 0;\n\t"
        "tcgen05.mma.cta_group::1.kind::f16 [%0], %1, %2, %3, {%4, %4, %4, %4}, p; }"
        :: "r"(d_tmem), "l"(a_desc), "l"(b_desc), "r"(idesc), "r"(0u), "r"(en)
        : "memory");
}
__device__ __forceinline__ void tc_ld_x32(uint32_t* r, uint32_t ta) {
    asm volatile(
        "tcgen05.ld.sync.aligned.32x32b.x32.b32 "
        "{%0,%1,%2,%3,%4,%5,%6,%7,%8,%9,%10,%11,%12,%13,%14,%15,"
        "%16,%17,%18,%19,%20,%21,%22,%23,%24,%25,%26,%27,%28,%29,%30,%31}, [%32];"
        : "=r"(r[0]), "=r"(r[1]), "=r"(r[2]), "=r"(r[3]), "=r"(r[4]), "=r"(r[5]),
          "=r"(r[6]), "=r"(r[7]), "=r"(r[8]), "=r"(r[9]), "=r"(r[10]), "=r"(r[11]),
          "=r"(r[12]), "=r"(r[13]), "=r"(r[14]), "=r"(r[15]), "=r"(r[16]), "=r"(r[17]),
          "=r"(r[18]), "=r"(r[19]), "=r"(r[20]), "=r"(r[21]), "=r"(r[22]), "=r"(r[23]),
          "=r"(r[24]), "=r"(r[25]), "=r"(r[26]), "=r"(r[27]), "=r"(r[28]), "=r"(r[29]),
          "=r"(r[30]), "=r"(r[31])
        : "r"(ta));
}
#define DESC_BASE ((2ull << 61) | (1ull << 46) | (64ull << 32) | (1ull << 16))
#define MK_DESC(a) (DESC_BASE | ((uint64_t)((a) >> 4) & 0x3FFF))
#define SWZ(o) ((o) ^ (((o) >> 3) & 0x70))
#define IDESC ((1u << 4) | (1u << 7) | (1u << 10) | (16u << 17) | (8u << 24))
#endif // TC_OK

// ---------------------------------------------------------------------------
// GEMM: Cout[M,N] = A[M,Kp] @ W[N,Kp]^T + bias   (bf16 in, fp32 out)
// tcgen05 path if available, else mma.sync (HMMA) path.
// ---------------------------------------------------------------------------
#define TILE_B    16384          // tcgen05: bytes per SMEM tile (128 x 128B)
#define STAGE_B   (2 * TILE_B)
#define GEMM_SMEM (1024 + 2 * STAGE_B)   // 66560 B (covers both paths)

__global__ __launch_bounds__(256, 1) void gemm_bf16(
    const __nv_bfloat16* __restrict__ A, const __nv_bfloat16* __restrict__ W,
    const float* __restrict__ bias, float* __restrict__ Cout,
    int M, int N, int Kp)
{
    extern __shared__ char sm[];
    const int tid = threadIdx.x;
    const int bm = blockIdx.y * 128;
    const int bn = blockIdx.x * 128;

#if TC_OK
    // ================= tcgen05 path =================
    const uint32_t smb = smem_u32(sm);
    if (tid < 32) TC_ALLOC(smb, 128);
    if (tid == 0) { MBAR_INIT(smb + 8, 1); MBAR_INIT(smb + 16, 1); }
    __syncthreads();
    uint32_t tmem;
    asm volatile("ld.shared.b32 %0, [%1];" : "=r"(tmem) : "r"(smb));

    const int nk = Kp >> 6;    // 64-col chunks

    auto load_chunk = [&](int c, int p) {
        const int k0 = c << 6;
        char* bufp = sm + 1024 + p * STAGE_B;
        #pragma unroll
        for (int t = 0; t < 4; t++) {
            int e = tid + t * 256;
            int r = e >> 3, c16 = e & 7;
            uint4 v = *(const uint4*)(A + (size_t)(bm + r) * Kp + k0 + c16 * 8);
            *(uint4*)(bufp + SWZ(r * 128 + c16 * 16)) = v;
        }
        #pragma unroll
        for (int t = 0; t < 4; t++) {
            int e = tid + t * 256;
            int r = e >> 3, c16 = e & 7;
            uint4 v = *(const uint4*)(W + (size_t)(bn + r) * Kp + k0 + c16 * 8);
            *(uint4*)(bufp + TILE_B + SWZ(r * 128 + c16 * 16)) = v;
        }
        FENCE_ASYNC_SHARED();
    };

    load_chunk(0, 0);
    __syncthreads();

    for (int c = 0; c < nk; c++) {
        const int p = c & 1;
        if (tid < 32 && elect_one()) {
            uint32_t base = smb + 1024 + p * STAGE_B;
            uint64_t ad = MK_DESC(base);
            uint64_t bd = MK_DESC(base + TILE_B);
            #pragma unroll
            for (int ks = 0; ks < 4; ks++)
                tc_mma_f16_ss(tmem, ad + ks * 2, bd + ks * 2, IDESC,
                              (uint32_t)((c > 0) | (ks > 0)));
            TC_COMMIT(smb + 8 + 8 * p);
        }
        if (c + 1 < nk) {
            if (c >= 1) MBAR_WAIT(smb + 8 + 8 * ((c - 1) & 1), ((c - 1) >> 1) & 1);
            load_chunk(c + 1, p ^ 1);
        }
        __syncthreads();
    }

    MBAR_WAIT(smb + 8 + 8 * ((nk - 1) & 1), ((nk - 1) >> 1) & 1);
    TC_FENCE_AFTER();

    if (tid < 128) {
        const int row = bm + tid;
        #pragma unroll
        for (int cb = 0; cb < 4; cb++) {
            uint32_t d[32];
            tc_ld_x32(d, tmem + cb * 32);
            TC_WAIT_LD();
            float* op = Cout + (size_t)row * N + bn + cb * 32;
            const float* bp = bias + bn + cb * 32;
            #pragma unroll
            for (int j = 0; j < 32; j += 4) {
                float4 r;
                r.x = __uint_as_float(d[j + 0]) + bp[j + 0];
                r.y = __uint_as_float(d[j + 1]) + bp[j + 1];
                r.z = __uint_as_float(d[j + 2]) + bp[j + 2];
                r.w = __uint_as_float(d[j + 3]) + bp[j + 3];
                *(float4*)(op + j) = r;
            }
        }
        TC_FENCE_BEFORE();
    }
    __syncthreads();
    if (tid < 32) TC_DEALLOC(tmem, 128);

#else
    // ================= mma.sync (HMMA bf16) fallback =================
    // SMEM stage: A[128][40] + B[128][40] bf16, 80B row pitch (conflict-free
    // ldmatrix), double-buffered with cp.async.
    const int warp = tid >> 5, lane = tid & 31;
    const int moff = (warp >> 1) * 32;    // 4 warps over M (32 rows each)
    const int noff = (warp & 1) * 64;     // 2 warps over N (64 cols each)

    float acc[2][8][4];
    #pragma unroll
    for (int a = 0; a < 2; a++)
        #pragma unroll
        for (int b = 0; b < 8; b++)
            #pragma unroll
            for (int c = 0; c < 4; c++) acc[a][b][c] = 0.f;

    auto issue_loads = [&](int c, int p) {
        const int k0 = c * 32;
        __nv_bfloat16* dstA = (__nv_bfloat16*)sm + p * 10240;
        __nv_bfloat16* dstB = dstA + 5120;
        #pragma unroll
        for (int t = 0; t < 2; t++) {
            int idx = tid + t * 256;               // 0..511
            int r = idx >> 2, c16 = idx & 3;
            uint32_t da = smem_u32(dstA + r * 40 + c16 * 8);
            const void* ga = A + (size_t)(bm + r) * Kp + k0 + c16 * 8;
            asm volatile("cp.async.cg.shared.global [%0], [%1], 16;"
                         :: "r"(da), "l"(ga) : "memory");
            uint32_t db = smem_u32(dstB + r * 40 + c16 * 8);
            const void* gb = W + (size_t)(bn + r) * Kp + k0 + c16 * 8;
            asm volatile("cp.async.cg.shared.global [%0], [%1], 16;"
                         :: "r"(db), "l"(gb) : "memory");
        }
    };

    issue_loads(0, 0);
    asm volatile("cp.async.commit_group;" ::: "memory");

    const int nk = Kp >> 5;     // 32-col chunks
    for (int c = 0; c < nk; c++) {
        asm volatile("cp.async.wait_group 0;" ::: "memory");
        __syncthreads();
        if (c + 1 < nk) issue_loads(c + 1, (c + 1) & 1);
        asm volatile("cp.async.commit_group;" ::: "memory");

        const __nv_bfloat16* pA = (const __nv_bfloat16*)sm + (c & 1) * 10240;
        const __nv_bfloat16* pB = pA + 5120;
        #pragma unroll
        for (int kh = 0; kh < 32; kh += 16) {
            uint32_t av[2][4];
            #pragma unroll
            for (int mb = 0; mb < 2; mb++) {
                int row = moff + mb * 16 + (lane & 7) + 8 * ((lane >> 3) & 1);
                int col = kh + 8 * (lane >> 4);
                uint32_t ad = smem_u32(pA + row * 40 + col);
                asm volatile("ldmatrix.sync.aligned.m8n8.x4.shared.b16 {%0,%1,%2,%3}, [%4];"
                             : "=r"(av[mb][0]), "=r"(av[mb][1]),
                               "=r"(av[mb][2]), "=r"(av[mb][3]) : "r"(ad));
            }
            #pragma unroll
            for (int nb = 0; nb < 8; nb++) {
                int row = noff + nb * 8 + (lane & 7);
                int col = kh + 8 * ((lane >> 3) & 1);
                uint32_t bd = smem_u32(pB + row * 40 + col);
                uint32_t b0, b1;
                asm volatile("ldmatrix.sync.aligned.m8n8.x2.shared.b16 {%0,%1}, [%2];"
                             : "=r"(b0), "=r"(b1) : "r"(bd));
                #pragma unroll
                for (int mb = 0; mb < 2; mb++)
                    asm volatile(
                        "mma.sync.aligned.m16n8k16.row.col.f32.bf16.bf16.f32 "
                        "{%0,%1,%2,%3},{%4,%5,%6,%7},{%8,%9},{%0,%1,%2,%3};"
                        : "+f"(acc[mb][nb][0]), "+f"(acc[mb][nb][1]),
                          "+f"(acc[mb][nb][2]), "+f"(acc[mb][nb][3])
                        : "r"(av[mb][0]), "r"(av[mb][1]), "r"(av[mb][2]), "r"(av[mb][3]),
                          "r"(b0), "r"(b1));
            }
        }
    }

    // epilogue: c0,c1 -> row r, cols c,c+1 ; c2,c3 -> row r+8
    const int r0 = lane >> 2, c0 = (lane & 3) * 2;
    #pragma unroll
    for (int mb = 0; mb < 2; mb++)
        #pragma unroll
        for (int nb = 0; nb < 8; nb++) {
            int row = bm + moff + mb * 16 + r0;
            int col = bn + noff + nb * 8 + c0;
            float2 v0 = make_float2(acc[mb][nb][0] + bias[col],
                                    acc[mb][nb][1] + bias[col + 1]);
            *(float2*)(Cout + (size_t)row * N + col) = v0;
            float2 v1 = make_float2(acc[mb][nb][2] + bias[col],
                                    acc[mb][nb][3] + bias[col + 1]);
            *(float2*)(Cout + (size_t)(row + 8) * N + col) = v1;
        }
#endif
}

// ---------------------------------------------------------------------------
// fp32 [R,K] -> bf16 wide [R,3K]: seg0 = hi always; lo at seg lo_seg, hi dup
// at the other. A operands: lo_seg=1 ([h|l|h]); W operands: lo_seg=2 ([h|h|l]).
// ---------------------------------------------------------------------------
__global__ __launch_bounds__(256) void split_wide(
    const float* __restrict__ src, __nv_bfloat16* __restrict__ dst,
    int K, int lo_seg, int n)
{
    int i = (blockIdx.x * 256 + threadIdx.x) * 4;
    if (i >= n) return;
    int r = i / K, j = i % K;
    float4 v = *(const float4*)(src + i);
    float f[4] = {v.x, v.y, v.z, v.w};
    size_t base = (size_t)r * 3 * K + j;
    size_t off_l = (lo_seg == 1) ? K : 2 * (size_t)K;
    size_t off_h2 = (lo_seg == 1) ? 2 * (size_t)K : K;
    #pragma unroll
    for (int q = 0; q < 4; q++) {
        __nv_bfloat16 h = __float2bfloat16(f[q]);
        __nv_bfloat16 l = __float2bfloat16(f[q] - __bfloat162float(h));
        dst[base + q] = h;
        dst[base + off_h2 + q] = h;
        dst[base + off_l + q] = l;
    }
}

// ---------------------------------------------------------------------------
// Flash attention (fp32, online softmax). Writes split y [h|l|h] wide rows.
// ---------------------------------------------------------------------------
#define ATTN_SMEM (4 * 64 * 65 * 4 + 64 * 4)

__global__ __launch_bounds__(256) void flash_attn(
    const float* __restrict__ qkv, const int* __restrict__ amask,
    __nv_bfloat16* __restrict__ ys)
{
    extern __shared__ float smf[];
    float* Qs = smf;
    float* Ks = Qs + 64 * 65;
    float* Vs = Ks + 64 * 65;
    float* Ps = Vs + 64 * 65;
    int*   smask = (int*)(Ps + 64 * 65);

    const int b = blockIdx.z, h = blockIdx.y, qt = blockIdx.x;
    const int q0 = qt * 64;
    const int tid = threadIdx.x;
    const int tx = tid & 15, ty = tid >> 4;
    const float* base = qkv + (size_t)b * T_ * C3_ + h * HD_;

    #pragma unroll
    for (int t = 0; t < 4; t++) {
        int idx = tid + t * 256;
        int r = idx >> 4;
        int c = (idx & 15) << 2;
        float4 v = *(const float4*)(base + (size_t)(q0 + r) * C3_ + c);
        Qs[r * 65 + c + 0] = v.x; Qs[r * 65 + c + 1] = v.y;
        Qs[r * 65 + c + 2] = v.z; Qs[r * 65 + c + 3] = v.w;
    }

    float m_i[4], l_i[4], o[4][4];
    #pragma unroll
    for (int i = 0; i < 4; i++) {
        m_i[i] = -1e30f; l_i[i] = 0.f;
        #pragma unroll
        for (int j = 0; j < 4; j++) o[i][j] = 0.f;
    }

    for (int kt = 0; kt <= qt; kt++) {
        const int k0 = kt * 64;
        __syncthreads();
        if (tid < 64) smask[tid] = amask[b * T_ + k0 + tid];
        #pragma unroll
        for (int t = 0; t < 4; t++) {
            int idx = tid + t * 256;
            int r = idx >> 4;
            int c = (idx & 15) << 2;
            float4 kv = *(const float4*)(base + C_ + (size_t)(k0 + r) * C3_ + c);
            Ks[r * 65 + c + 0] = kv.x; Ks[r * 65 + c + 1] = kv.y;
            Ks[r * 65 + c + 2] = kv.z; Ks[r * 65 + c + 3] = kv.w;
            float4 vv = *(const float4*)(base + 2 * C_ + (size_t)(k0 + r) * C3_ + c);
            Vs[r * 65 + c + 0] = vv.x; Vs[r * 65 + c + 1] = vv.y;
            Vs[r * 65 + c + 2] = vv.z; Vs[r * 65 + c + 3] = vv.w;
        }
        __syncthreads();
        if (smask[0] == 0) break;

        float s[4][4];
        #pragma unroll
        for (int i = 0; i < 4; i++)
            #pragma unroll
            for (int j = 0; j < 4; j++) s[i][j] = 0.f;
        #pragma unroll 8
        for (int d = 0; d < 64; d++) {
            float qv[4], kv[4];
            #pragma unroll
            for (int i = 0; i < 4; i++) qv[i] = Qs[(ty * 4 + i) * 65 + d];
            #pragma unroll
            for (int j = 0; j < 4; j++) kv[j] = Ks[(tx * 4 + j) * 65 + d];
            #pragma unroll
            for (int i = 0; i < 4; i++)
                #pragma unroll
                for (int j = 0; j < 4; j++)
                    s[i][j] += qv[i] * kv[j];
        }

        #pragma unroll
        for (int i = 0; i < 4; i++) {
            const int qr = q0 + ty * 4 + i;
            float tm = -1e30f;
            #pragma unroll
            for (int j = 0; j < 4; j++) {
                int kc = k0 + tx * 4 + j;
                float v = (kc <= qr && smask[tx * 4 + j]) ? s[i][j] * 0.125f : -1e30f;
                s[i][j] = v;
                tm = fmaxf(tm, v);
            }
            #pragma unroll
            for (int off = 8; off; off >>= 1)
                tm = fmaxf(tm, __shfl_xor_sync(0xffffffffu, tm, off, 16));
            float mn = fmaxf(m_i[i], tm);
            float corr = __expf(m_i[i] - mn);
            float rs = 0.f;
            #pragma unroll
            for (int j = 0; j < 4; j++) {
                float p = __expf(s[i][j] - mn);
                s[i][j] = p;
                rs += p;
            }
            #pragma unroll
            for (int off = 8; off; off >>= 1)
                rs += __shfl_xor_sync(0xffffffffu, rs, off, 16);
            l_i[i] = l_i[i] * corr + rs;
            m_i[i] = mn;
            #pragma unroll
            for (int j = 0; j < 4; j++) {
                o[i][j] *= corr;
                Ps[(ty * 4 + i) * 65 + tx * 4 + j] = s[i][j];
            }
        }
        __syncthreads();

        #pragma unroll 8
        for (int kk = 0; kk < 64; kk++) {
            float pv[4], vv[4];
            #pragma unroll
            for (int i = 0; i < 4; i++) pv[i] = Ps[(ty * 4 + i) * 65 + kk];
            #pragma unroll
            for (int j = 0; j < 4; j++) vv[j] = Vs[kk * 65 + tx * 4 + j];
            #pragma unroll
            for (int i = 0; i < 4; i++)
                #pragma unroll
                for (int j = 0; j < 4; j++)
                    o[i][j] += pv[i] * vv[j];
        }
    }

    #pragma unroll
    for (int i = 0; i < 4; i++) {
        int qr = q0 + ty * 4 + i;
        int qm = amask[b * T_ + qr];
        float inv = (qm && l_i[i] > 0.f) ? (1.f / l_i[i]) : 0.f;
        size_t rowb = ((size_t)b * T_ + qr) * KP_;
        int col = h * HD_ + tx * 4;
        #pragma unroll
        for (int j = 0; j < 4; j++) {
            float val = o[i][j] * inv;
            __nv_bfloat16 hh = __float2bfloat16(val);
            __nv_bfloat16 ll = __float2bfloat16(val - __bfloat162float(hh));
            ys[rowb + col + j]            = hh;   // hi
            ys[rowb + C_ + col + j]       = ll;   // lo
            ys[rowb + 2 * C_ + col + j]   = hh;   // hi dup
        }
    }
}

// ---------------------------------------------------------------------------
extern "C" void kernel_launch(void* const* d_in, const int* in_sizes, int n_in,
                              void* d_out, int out_size)
{
    const float* x    = (const float*)d_in[0];
    const int*   am   = (const int*)  d_in[1];
    const float* Wqkv = (const float*)d_in[2];
    const float* bqkv = (const float*)d_in[3];
    const float* Wo   = (const float*)d_in[4];
    const float* bo   = (const float*)d_in[5];
    float* out = (float*)d_out;

    float* qkv;
    __nv_bfloat16 *xs, *wqs, *wos, *ys;
    cudaGetSymbolAddress((void**)&qkv, g_qkv);
    cudaGetSymbolAddress((void**)&xs,  g_xs);
    cudaGetSymbolAddress((void**)&wqs, g_wqs);
    cudaGetSymbolAddress((void**)&wos, g_wos);
    cudaGetSymbolAddress((void**)&ys,  g_ys);

    cudaFuncSetAttribute(gemm_bf16, cudaFuncAttributeMaxDynamicSharedMemorySize, GEMM_SMEM);
    cudaFuncSetAttribute(flash_attn, cudaFuncAttributeMaxDynamicSharedMemorySize, ATTN_SMEM);

    int nx = M_ * C_, nwq = C3_ * C_, nwo = C_ * C_;
    split_wide<<<nx  / 1024, 256>>>(x,    xs,  C_, 1, nx);
    split_wide<<<nwq / 1024, 256>>>(Wqkv, wqs, C_, 2, nwq);
    split_wide<<<nwo / 1024, 256>>>(Wo,   wos, C_, 2, nwo);

    gemm_bf16<<<dim3(C3_ / 128, M_ / 128), 256, GEMM_SMEM>>>(
        xs, wqs, bqkv, qkv, M_, C3_, KP_);
    flash_attn<<<dim3(T_ / 64, H_, B_), 256, ATTN_SMEM>>>(qkv, am, ys);
    gemm_bf16<<<dim3(C_ / 128, M_ / 128), 256, GEMM_SMEM>>>(
        ys, wos, bo, out, M_, C_, KP_);
}

// round 4
// speedup vs baseline: 2.1747x; 1.6092x over previous
#include <cuda_runtime.h>
#include <cuda_bf16.h>
#include <cstdint>

// Problem constants
#define B_   4
#define T_   2048
#define C_   1024
#define H_   16
#define HD_  64
#define M_   (B_ * T_)          // 8192
#define C3_  (3 * C_)           // 3072
#define KP_  (3 * C_)           // 3072 concat-K

// tcgen05 only if the device pass has full sm_103a features
#if !defined(__CUDA_ARCH__) || defined(__CUDA_ARCH_FEAT_SM103_ALL)
#define TC_OK 1
#else
#define TC_OK 0
#endif

// ---------------------------------------------------------------------------
// Scratch
// ---------------------------------------------------------------------------
__device__ float g_qkv[(size_t)M_ * C3_];
__device__ __nv_bfloat16 g_xs [(size_t)M_  * KP_];
__device__ __nv_bfloat16 g_wqs[(size_t)C3_ * KP_];
__device__ __nv_bfloat16 g_wos[(size_t)C_  * KP_];
__device__ __nv_bfloat16 g_ys [(size_t)M_  * KP_];
__device__ int g_len[B_];

// ---------------------------------------------------------------------------
// Helpers
// ---------------------------------------------------------------------------
__device__ __forceinline__ uint32_t smem_u32(const void* p) {
    uint32_t a;
    asm("{ .reg .u64 t; cvta.to.shared.u64 t, %1; cvt.u32.u64 %0, t; }"
        : "=r"(a) : "l"(p));
    return a;
}

#define MMA16816(C, A, b0, b1)                                                \
    asm volatile(                                                             \
        "mma.sync.aligned.m16n8k16.row.col.f32.bf16.bf16.f32 "                \
        "{%0,%1,%2,%3},{%4,%5,%6,%7},{%8,%9},{%0,%1,%2,%3};"                  \
        : "+f"((C)[0]), "+f"((C)[1]), "+f"((C)[2]), "+f"((C)[3])              \
        : "r"((A)[0]), "r"((A)[1]), "r"((A)[2]), "r"((A)[3]),                 \
          "r"(b0), "r"(b1))

#define LDSM_X4(R, addr)                                                      \
    asm volatile("ldmatrix.sync.aligned.m8n8.x4.shared.b16 {%0,%1,%2,%3}, [%4];" \
        : "=r"((R)[0]), "=r"((R)[1]), "=r"((R)[2]), "=r"((R)[3]) : "r"(addr))

#define LDSM_X2(r0, r1, addr)                                                 \
    asm volatile("ldmatrix.sync.aligned.m8n8.x2.shared.b16 {%0,%1}, [%2];"    \
        : "=r"(r0), "=r"(r1) : "r"(addr))

#define LDSM_X2T(r0, r1, addr)                                                \
    asm volatile("ldmatrix.sync.aligned.m8n8.x2.trans.shared.b16 {%0,%1}, [%2];" \
        : "=r"(r0), "=r"(r1) : "r"(addr))

// pack two fp32 -> bf16x2 (a = low), plus residual pair
__device__ __forceinline__ uint32_t pack_hi(float a, float b) {
    __nv_bfloat162 v = __floats2bfloat162_rn(a, b);
    return *reinterpret_cast<uint32_t*>(&v);
}
__device__ __forceinline__ uint32_t pack_res(float a, float b, uint32_t hp) {
    __nv_bfloat162 h = *reinterpret_cast<__nv_bfloat162*>(&hp);
    __nv_bfloat162 v = __floats2bfloat162_rn(a - __bfloat162float(h.x),
                                             b - __bfloat162float(h.y));
    return *reinterpret_cast<uint32_t*>(&v);
}

#if TC_OK
__device__ __forceinline__ uint32_t elect_one() {
    uint32_t p;
    asm volatile("{ .reg .pred p; elect.sync _|p, 0xFFFFFFFF; selp.b32 %0, 1, 0, p; }"
                 : "=r"(p));
    return p;
}
#define TC_ALLOC(smem_addr, n)  asm volatile("tcgen05.alloc.cta_group::1.sync.aligned.shared::cta.b32 [%0], %1;" :: "r"(smem_addr), "r"(n) : "memory")
#define TC_DEALLOC(tmem, n)     asm volatile("tcgen05.dealloc.cta_group::1.sync.aligned.b32 %0, %1;" :: "r"(tmem), "r"(n))
#define TC_COMMIT(mbar)         asm volatile("tcgen05.commit.cta_group::1.mbarrier::arrive::one.shared::cluster.b64 [%0];" :: "r"(mbar) : "memory")
#define TC_FENCE_AFTER()        asm volatile("tcgen05.fence::after_thread_sync;" ::: "memory")
#define TC_FENCE_BEFORE()       asm volatile("tcgen05.fence::before_thread_sync;" ::: "memory")
#define TC_WAIT_LD()            asm volatile("tcgen05.wait::ld.sync.aligned;" ::: "memory")
#define MBAR_INIT(mbar, cnt)    asm volatile("mbarrier.init.shared.b64 [%0], %1;" :: "r"(mbar), "r"(cnt) : "memory")
#define FENCE_ASYNC_SHARED()    asm volatile("fence.proxy.async.shared::cta;" ::: "memory")
#define MBAR_WAIT(mbar, parity) do {                                          \
    uint32_t _m = (mbar), _p = (parity), _d;                                  \
    asm volatile("{ .reg .pred p; mbarrier.try_wait.parity.acquire.cta.shared::cta.b64 p, [%1], %2; selp.b32 %0, 1, 0, p; }" \
                 : "=r"(_d) : "r"(_m), "r"(_p) : "memory");                   \
    if (!_d) {                                                                \
        asm volatile("{ .reg .pred P1; WL_%=:\n\t"                            \
            "mbarrier.try_wait.parity.acquire.cta.shared::cta.b64 P1, [%0], %1, 0x989680;\n\t" \
            "@P1 bra.uni WD_%=; bra.uni WL_%=; WD_%=: }"                      \
            :: "r"(_m), "r"(_p) : "memory");                                  \
    }                                                                          \
} while (0)
__device__ __forceinline__ void tc_mma_f16_ss(
    uint32_t d_tmem, uint64_t a_desc, uint64_t b_desc, uint32_t idesc, uint32_t en)
{
    asm volatile(
        "{ .reg .pred p; setp.ne.u32 p, %5, 0;\n\t"
        "tcgen05.mma.cta_group::1.kind::f16 [%0], %1, %2, %3, {%4, %4, %4, %4}, p; }"
        :: "r"(d_tmem), "l"(a_desc), "l"(b_desc), "r"(idesc), "r"(0u), "r"(en)
        : "memory");
}
__device__ __forceinline__ void tc_ld_x32(uint32_t* r, uint32_t ta) {
    asm volatile(
        "tcgen05.ld.sync.aligned.32x32b.x32.b32 "
        "{%0,%1,%2,%3,%4,%5,%6,%7,%8,%9,%10,%11,%12,%13,%14,%15,"
        "%16,%17,%18,%19,%20,%21,%22,%23,%24,%25,%26,%27,%28,%29,%30,%31}, [%32];"
        : "=r"(r[0]), "=r"(r[1]), "=r"(r[2]), "=r"(r[3]), "=r"(r[4]), "=r"(r[5]),
          "=r"(r[6]), "=r"(r[7]), "=r"(r[8]), "=r"(r[9]), "=r"(r[10]), "=r"(r[11]),
          "=r"(r[12]), "=r"(r[13]), "=r"(r[14]), "=r"(r[15]), "=r"(r[16]), "=r"(r[17]),
          "=r"(r[18]), "=r"(r[19]), "=r"(r[20]), "=r"(r[21]), "=r"(r[22]), "=r"(r[23]),
          "=r"(r[24]), "=r"(r[25]), "=r"(r[26]), "=r"(r[27]), "=r"(r[28]), "=r"(r[29]),
          "=r"(r[30]), "=r"(r[31])
        : "r"(ta));
}
#define DESC_BASE ((2ull << 61) | (1ull << 46) | (64ull << 32) | (1ull << 16))
#define MK_DESC(a) (DESC_BASE | ((uint64_t)((a) >> 4) & 0x3FFF))
#define SWZ(o) ((o) ^ (((o) >> 3) & 0x70))
#define IDESC ((1u << 4) | (1u << 7) | (1u << 10) | (16u << 17) | (8u << 24))
#endif // TC_OK

// ---------------------------------------------------------------------------
// GEMM (unchanged from Round 3): Cout[M,N] = A[M,Kp] @ W[N,Kp]^T + bias
// ---------------------------------------------------------------------------
#define TILE_B    16384
#define STAGE_B   (2 * TILE_B)
#define GEMM_SMEM (1024 + 2 * STAGE_B)

__global__ __launch_bounds__(256, 1) void gemm_bf16(
    const __nv_bfloat16* __restrict__ A, const __nv_bfloat16* __restrict__ W,
    const float* __restrict__ bias, float* __restrict__ Cout,
    int M, int N, int Kp)
{
    extern __shared__ char sm[];
    const int tid = threadIdx.x;
    const int bm = blockIdx.y * 128;
    const int bn = blockIdx.x * 128;

#if TC_OK
    const uint32_t smb = smem_u32(sm);
    if (tid < 32) TC_ALLOC(smb, 128);
    if (tid == 0) { MBAR_INIT(smb + 8, 1); MBAR_INIT(smb + 16, 1); }
    __syncthreads();
    uint32_t tmem;
    asm volatile("ld.shared.b32 %0, [%1];" : "=r"(tmem) : "r"(smb));

    const int nk = Kp >> 6;
    auto load_chunk = [&](int c, int p) {
        const int k0 = c << 6;
        char* bufp = sm + 1024 + p * STAGE_B;
        #pragma unroll
        for (int t = 0; t < 4; t++) {
            int e = tid + t * 256;
            int r = e >> 3, c16 = e & 7;
            uint4 v = *(const uint4*)(A + (size_t)(bm + r) * Kp + k0 + c16 * 8);
            *(uint4*)(bufp + SWZ(r * 128 + c16 * 16)) = v;
        }
        #pragma unroll
        for (int t = 0; t < 4; t++) {
            int e = tid + t * 256;
            int r = e >> 3, c16 = e & 7;
            uint4 v = *(const uint4*)(W + (size_t)(bn + r) * Kp + k0 + c16 * 8);
            *(uint4*)(bufp + TILE_B + SWZ(r * 128 + c16 * 16)) = v;
        }
        FENCE_ASYNC_SHARED();
    };
    load_chunk(0, 0);
    __syncthreads();
    for (int c = 0; c < nk; c++) {
        const int p = c & 1;
        if (tid < 32 && elect_one()) {
            uint32_t base = smb + 1024 + p * STAGE_B;
            uint64_t ad = MK_DESC(base);
            uint64_t bd = MK_DESC(base + TILE_B);
            #pragma unroll
            for (int ks = 0; ks < 4; ks++)
                tc_mma_f16_ss(tmem, ad + ks * 2, bd + ks * 2, IDESC,
                              (uint32_t)((c > 0) | (ks > 0)));
            TC_COMMIT(smb + 8 + 8 * p);
        }
        if (c + 1 < nk) {
            if (c >= 1) MBAR_WAIT(smb + 8 + 8 * ((c - 1) & 1), ((c - 1) >> 1) & 1);
            load_chunk(c + 1, p ^ 1);
        }
        __syncthreads();
    }
    MBAR_WAIT(smb + 8 + 8 * ((nk - 1) & 1), ((nk - 1) >> 1) & 1);
    TC_FENCE_AFTER();
    if (tid < 128) {
        const int row = bm + tid;
        #pragma unroll
        for (int cb = 0; cb < 4; cb++) {
            uint32_t d[32];
            tc_ld_x32(d, tmem + cb * 32);
            TC_WAIT_LD();
            float* op = Cout + (size_t)row * N + bn + cb * 32;
            const float* bp = bias + bn + cb * 32;
            #pragma unroll
            for (int j = 0; j < 32; j += 4) {
                float4 r;
                r.x = __uint_as_float(d[j + 0]) + bp[j + 0];
                r.y = __uint_as_float(d[j + 1]) + bp[j + 1];
                r.z = __uint_as_float(d[j + 2]) + bp[j + 2];
                r.w = __uint_as_float(d[j + 3]) + bp[j + 3];
                *(float4*)(op + j) = r;
            }
        }
        TC_FENCE_BEFORE();
    }
    __syncthreads();
    if (tid < 32) TC_DEALLOC(tmem, 128);
#else
    const int warp = tid >> 5, lane = tid & 31;
    const int moff = (warp >> 1) * 32;
    const int noff = (warp & 1) * 64;

    float acc[2][8][4];
    #pragma unroll
    for (int a = 0; a < 2; a++)
        #pragma unroll
        for (int b = 0; b < 8; b++)
            #pragma unroll
            for (int c = 0; c < 4; c++) acc[a][b][c] = 0.f;

    auto issue_loads = [&](int c, int p) {
        const int k0 = c * 32;
        __nv_bfloat16* dstA = (__nv_bfloat16*)sm + p * 10240;
        __nv_bfloat16* dstB = dstA + 5120;
        #pragma unroll
        for (int t = 0; t < 2; t++) {
            int idx = tid + t * 256;
            int r = idx >> 2, c16 = idx & 3;
            uint32_t da = smem_u32(dstA + r * 40 + c16 * 8);
            const void* ga = A + (size_t)(bm + r) * Kp + k0 + c16 * 8;
            asm volatile("cp.async.cg.shared.global [%0], [%1], 16;"
                         :: "r"(da), "l"(ga) : "memory");
            uint32_t db = smem_u32(dstB + r * 40 + c16 * 8);
            const void* gb = W + (size_t)(bn + r) * Kp + k0 + c16 * 8;
            asm volatile("cp.async.cg.shared.global [%0], [%1], 16;"
                         :: "r"(db), "l"(gb) : "memory");
        }
    };

    issue_loads(0, 0);
    asm volatile("cp.async.commit_group;" ::: "memory");

    const int nk = Kp >> 5;
    for (int c = 0; c < nk; c++) {
        asm volatile("cp.async.wait_group 0;" ::: "memory");
        __syncthreads();
        if (c + 1 < nk) issue_loads(c + 1, (c + 1) & 1);
        asm volatile("cp.async.commit_group;" ::: "memory");

        const __nv_bfloat16* pA = (const __nv_bfloat16*)sm + (c & 1) * 10240;
        const __nv_bfloat16* pB = pA + 5120;
        #pragma unroll
        for (int kh = 0; kh < 32; kh += 16) {
            uint32_t av[2][4];
            #pragma unroll
            for (int mb = 0; mb < 2; mb++) {
                int row = moff + mb * 16 + (lane & 7) + 8 * ((lane >> 3) & 1);
                int col = kh + 8 * (lane >> 4);
                uint32_t ad = smem_u32(pA + row * 40 + col);
                LDSM_X4(av[mb], ad);
            }
            #pragma unroll
            for (int nb = 0; nb < 8; nb++) {
                int row = noff + nb * 8 + (lane & 7);
                int col = kh + 8 * ((lane >> 3) & 1);
                uint32_t bd = smem_u32(pB + row * 40 + col);
                uint32_t b0, b1;
                LDSM_X2(b0, b1, bd);
                #pragma unroll
                for (int mb = 0; mb < 2; mb++)
                    MMA16816(acc[mb][nb], av[mb], b0, b1);
            }
        }
    }

    const int r0 = lane >> 2, c0 = (lane & 3) * 2;
    #pragma unroll
    for (int mb = 0; mb < 2; mb++)
        #pragma unroll
        for (int nb = 0; nb < 8; nb++) {
            int row = bm + moff + mb * 16 + r0;
            int col = bn + noff + nb * 8 + c0;
            float2 v0 = make_float2(acc[mb][nb][0] + bias[col],
                                    acc[mb][nb][1] + bias[col + 1]);
            *(float2*)(Cout + (size_t)row * N + col) = v0;
            float2 v1 = make_float2(acc[mb][nb][2] + bias[col],
                                    acc[mb][nb][3] + bias[col + 1]);
            *(float2*)(Cout + (size_t)(row + 8) * N + col) = v1;
        }
#endif
}

// ---------------------------------------------------------------------------
// per-batch valid length
// ---------------------------------------------------------------------------
__global__ void compute_len(const int* __restrict__ am, int* __restrict__ out) {
    __shared__ int red[8];
    int b = blockIdx.x, acc = 0;
    for (int i = threadIdx.x; i < T_; i += 256) acc += am[b * T_ + i];
    #pragma unroll
    for (int o = 16; o; o >>= 1) acc += __shfl_xor_sync(0xffffffffu, acc, o);
    if ((threadIdx.x & 31) == 0) red[threadIdx.x >> 5] = acc;
    __syncthreads();
    if (threadIdx.x == 0) {
        int v = 0;
        #pragma unroll
        for (int i = 0; i < 8; i++) v += red[i];
        out[b] = v;
    }
}

// ---------------------------------------------------------------------------
// fp32 [R,K] -> bf16 wide [R,3K]
// ---------------------------------------------------------------------------
__global__ __launch_bounds__(256) void split_wide(
    const float* __restrict__ src, __nv_bfloat16* __restrict__ dst,
    int K, int lo_seg, int n)
{
    int i = (blockIdx.x * 256 + threadIdx.x) * 4;
    if (i >= n) return;
    int r = i / K, j = i % K;
    float4 v = *(const float4*)(src + i);
    float f[4] = {v.x, v.y, v.z, v.w};
    size_t base = (size_t)r * 3 * K + j;
    size_t off_l = (lo_seg == 1) ? K : 2 * (size_t)K;
    size_t off_h2 = (lo_seg == 1) ? 2 * (size_t)K : K;
    #pragma unroll
    for (int q = 0; q < 4; q++) {
        __nv_bfloat16 h = __float2bfloat16(f[q]);
        __nv_bfloat16 l = __float2bfloat16(f[q] - __bfloat162float(h));
        dst[base + q] = h;
        dst[base + off_h2 + q] = h;
        dst[base + off_l + q] = l;
    }
}

// ---------------------------------------------------------------------------
// Tensor-core flash attention: 128 q-rows/CTA, 8 warps x 16 rows, 64-key tiles
// S = Qh·Kh + Ql·Kh + Qh·Kl ; O += Ph·Vh + Pl·Vh + Ph·Vl (fp32 accum)
// ---------------------------------------------------------------------------
#define PITCH 72

__global__ __launch_bounds__(256, 1) void flash_attn_tc(
    const float* __restrict__ qkv, const int* __restrict__ lenp,
    __nv_bfloat16* __restrict__ ys)
{
    __shared__ __nv_bfloat16 sbuf[4 * 64 * PITCH];
    __nv_bfloat16* Kh = sbuf;
    __nv_bfloat16* Kl = sbuf + 64 * PITCH;
    __nv_bfloat16* Vh = sbuf + 2 * 64 * PITCH;
    __nv_bfloat16* Vl = sbuf + 3 * 64 * PITCH;
    __nv_bfloat16* Qh = sbuf;                    // staging alias (pre-loop)
    __nv_bfloat16* Ql = sbuf + 128 * PITCH;

    const int b = blockIdx.z, h = blockIdx.y, qt = blockIdx.x;
    const int q0 = qt * 128;
    const int tid = threadIdx.x;
    const int warp = tid >> 5, lane = tid & 31;
    const int len = lenp[b];
    const float* base = qkv + (size_t)b * T_ * C3_ + h * HD_;

    // ---- stage Q fp32 -> hi/lo bf16 ----
    #pragma unroll
    for (int t = 0; t < 8; t++) {
        int e = tid + t * 256;               // 0..2047 float4
        int r = e >> 4, c4 = e & 15;
        float4 v = *(const float4*)(base + (size_t)(q0 + r) * C3_ + c4 * 4);
        float f[4] = {v.x, v.y, v.z, v.w};
        #pragma unroll
        for (int j = 0; j < 4; j++) {
            __nv_bfloat16 hi = __float2bfloat16(f[j]);
            Qh[r * PITCH + c4 * 4 + j] = hi;
            Ql[r * PITCH + c4 * 4 + j] = __float2bfloat16(f[j] - __bfloat162float(hi));
        }
    }
    __syncthreads();

    // ---- extract Q fragments (A m16k16, 4 k-steps) ----
    uint32_t qh[4][4], ql[4][4];
    {
        int row = warp * 16 + (lane & 7) + 8 * ((lane >> 3) & 1);
        #pragma unroll
        for (int ks = 0; ks < 4; ks++) {
            int col = ks * 16 + 8 * (lane >> 4);
            LDSM_X4(qh[ks], smem_u32(Qh + row * PITCH + col));
            LDSM_X4(ql[ks], smem_u32(Ql + row * PITCH + col));
        }
    }
    __syncthreads();

    float m_[2] = {-1e30f, -1e30f}, l_[2] = {0.f, 0.f};
    float O[8][4] = {};

    const int kt_len = (len + 63) >> 6;
    const int kt_max = min(2 * qt + 1, kt_len - 1);
    const int wrow_max = q0 + warp * 16 + 15;
    const int r0 = lane >> 2, cb = (lane & 3) * 2;
    const int row0 = q0 + warp * 16 + r0, row1 = row0 + 8;

    for (int kt = 0; kt <= kt_max; kt++) {
        const int k0 = kt * 64;
        __syncthreads();
        // load K,V tiles (64x64 fp32 each) -> hi/lo bf16 smem
        #pragma unroll
        for (int t = 0; t < 4; t++) {
            int e = tid + t * 256;           // 0..1023 float4
            int r = e >> 4, c4 = e & 15;
            float4 kv = *(const float4*)(base + C_ + (size_t)(k0 + r) * C3_ + c4 * 4);
            float4 vv = *(const float4*)(base + 2 * C_ + (size_t)(k0 + r) * C3_ + c4 * 4);
            float fk[4] = {kv.x, kv.y, kv.z, kv.w};
            float fv[4] = {vv.x, vv.y, vv.z, vv.w};
            #pragma unroll
            for (int j = 0; j < 4; j++) {
                __nv_bfloat16 hk = __float2bfloat16(fk[j]);
                Kh[r * PITCH + c4 * 4 + j] = hk;
                Kl[r * PITCH + c4 * 4 + j] = __float2bfloat16(fk[j] - __bfloat162float(hk));
                __nv_bfloat16 hv = __float2bfloat16(fv[j]);
                Vh[r * PITCH + c4 * 4 + j] = hv;
                Vl[r * PITCH + c4 * 4 + j] = __float2bfloat16(fv[j] - __bfloat162float(hv));
            }
        }
        __syncthreads();
        if (k0 > wrow_max) continue;        // tile fully above this warp's diag

        // ---- S = Q K^T (3 split terms) ----
        float S[8][4] = {};
        {
            int krow = (lane & 7);
            int kcol8 = 8 * ((lane >> 3) & 1);
            #pragma unroll
            for (int nb = 0; nb < 8; nb++) {
                #pragma unroll
                for (int ks = 0; ks < 4; ks++) {
                    uint32_t bh0, bh1, bl0, bl1;
                    uint32_t ah = smem_u32(Kh + (nb * 8 + krow) * PITCH + ks * 16 + kcol8);
                    uint32_t al = smem_u32(Kl + (nb * 8 + krow) * PITCH + ks * 16 + kcol8);
                    LDSM_X2(bh0, bh1, ah);
                    LDSM_X2(bl0, bl1, al);
                    MMA16816(S[nb], qh[ks], bh0, bh1);
                    MMA16816(S[nb], ql[ks], bh0, bh1);
                    MMA16816(S[nb], qh[ks], bl0, bl1);
                }
            }
        }

        // ---- mask + online softmax ----
        float ml0 = -1e30f, ml1 = -1e30f;
        #pragma unroll
        for (int nb = 0; nb < 8; nb++) {
            int c0 = k0 + nb * 8 + cb;
            S[nb][0] = (c0     <= row0 && c0     < len) ? S[nb][0] * 0.125f : -1e30f;
            S[nb][1] = (c0 + 1 <= row0 && c0 + 1 < len) ? S[nb][1] * 0.125f : -1e30f;
            S[nb][2] = (c0     <= row1 && c0     < len) ? S[nb][2] * 0.125f : -1e30f;
            S[nb][3] = (c0 + 1 <= row1 && c0 + 1 < len) ? S[nb][3] * 0.125f : -1e30f;
            ml0 = fmaxf(ml0, fmaxf(S[nb][0], S[nb][1]));
            ml1 = fmaxf(ml1, fmaxf(S[nb][2], S[nb][3]));
        }
        ml0 = fmaxf(ml0, __shfl_xor_sync(0xffffffffu, ml0, 1));
        ml0 = fmaxf(ml0, __shfl_xor_sync(0xffffffffu, ml0, 2));
        ml1 = fmaxf(ml1, __shfl_xor_sync(0xffffffffu, ml1, 1));
        ml1 = fmaxf(ml1, __shfl_xor_sync(0xffffffffu, ml1, 2));
        float mn0 = fmaxf(m_[0], ml0), mn1 = fmaxf(m_[1], ml1);
        float corr0 = __expf(m_[0] - mn0), corr1 = __expf(m_[1] - mn1);
        float ls0 = 0.f, ls1 = 0.f;
        #pragma unroll
        for (int nb = 0; nb < 8; nb++) {
            S[nb][0] = __expf(S[nb][0] - mn0); ls0 += S[nb][0];
            S[nb][1] = __expf(S[nb][1] - mn0); ls0 += S[nb][1];
            S[nb][2] = __expf(S[nb][2] - mn1); ls1 += S[nb][2];
            S[nb][3] = __expf(S[nb][3] - mn1); ls1 += S[nb][3];
        }
        ls0 += __shfl_xor_sync(0xffffffffu, ls0, 1);
        ls0 += __shfl_xor_sync(0xffffffffu, ls0, 2);
        ls1 += __shfl_xor_sync(0xffffffffu, ls1, 1);
        ls1 += __shfl_xor_sync(0xffffffffu, ls1, 2);
        l_[0] = l_[0] * corr0 + ls0;
        l_[1] = l_[1] * corr1 + ls1;
        m_[0] = mn0; m_[1] = mn1;
        #pragma unroll
        for (int nb = 0; nb < 8; nb++) {
            O[nb][0] *= corr0; O[nb][1] *= corr0;
            O[nb][2] *= corr1; O[nb][3] *= corr1;
        }

        // ---- O += P V (3 split terms); S accum reused as A fragments ----
        {
            int vrow8 = (lane & 7) + 8 * ((lane >> 3) & 1);
            #pragma unroll
            for (int ks = 0; ks < 4; ks++) {
                uint32_t ph[4], pl[4];
                ph[0] = pack_hi(S[2 * ks][0], S[2 * ks][1]);
                ph[1] = pack_hi(S[2 * ks][2], S[2 * ks][3]);
                ph[2] = pack_hi(S[2 * ks + 1][0], S[2 * ks + 1][1]);
                ph[3] = pack_hi(S[2 * ks + 1][2], S[2 * ks + 1][3]);
                pl[0] = pack_res(S[2 * ks][0], S[2 * ks][1], ph[0]);
                pl[1] = pack_res(S[2 * ks][2], S[2 * ks][3], ph[1]);
                pl[2] = pack_res(S[2 * ks + 1][0], S[2 * ks + 1][1], ph[2]);
                pl[3] = pack_res(S[2 * ks + 1][2], S[2 * ks + 1][3], ph[3]);
                #pragma unroll
                for (int nb = 0; nb < 8; nb++) {
                    uint32_t vh0, vh1, vl0, vl1;
                    uint32_t av = smem_u32(Vh + (ks * 16 + vrow8) * PITCH + nb * 8);
                    uint32_t al = smem_u32(Vl + (ks * 16 + vrow8) * PITCH + nb * 8);
                    LDSM_X2T(vh0, vh1, av);
                    LDSM_X2T(vl0, vl1, al);
                    MMA16816(O[nb], ph, vh0, vh1);
                    MMA16816(O[nb], pl, vh0, vh1);
                    MMA16816(O[nb], ph, vl0, vl1);
                }
            }
        }
    }

    // ---- epilogue: normalize, split hi/lo, store wide rows [h|l|h] ----
    float inv0 = (row0 < len && l_[0] > 0.f) ? (1.f / l_[0]) : 0.f;
    float inv1 = (row1 < len && l_[1] > 0.f) ? (1.f / l_[1]) : 0.f;
    size_t rb0 = ((size_t)b * T_ + row0) * KP_;
    size_t rb1 = ((size_t)b * T_ + row1) * KP_;
    #pragma unroll
    for (int nb = 0; nb < 8; nb++) {
        int hcol = h * HD_ + nb * 8 + cb;
        uint32_t h0 = pack_hi(O[nb][0] * inv0, O[nb][1] * inv0);
        uint32_t l0 = pack_res(O[nb][0] * inv0, O[nb][1] * inv0, h0);
        uint32_t h1 = pack_hi(O[nb][2] * inv1, O[nb][3] * inv1);
        uint32_t l1 = pack_res(O[nb][2] * inv1, O[nb][3] * inv1, h1);
        *(uint32_t*)(ys + rb0 + hcol)          = h0;
        *(uint32_t*)(ys + rb0 + C_ + hcol)     = l0;
        *(uint32_t*)(ys + rb0 + 2 * C_ + hcol) = h0;
        *(uint32_t*)(ys + rb1 + hcol)          = h1;
        *(uint32_t*)(ys + rb1 + C_ + hcol)     = l1;
        *(uint32_t*)(ys + rb1 + 2 * C_ + hcol) = h1;
    }
}

// ---------------------------------------------------------------------------
extern "C" void kernel_launch(void* const* d_in, const int* in_sizes, int n_in,
                              void* d_out, int out_size)
{
    const float* x    = (const float*)d_in[0];
    const int*   am   = (const int*)  d_in[1];
    const float* Wqkv = (const float*)d_in[2];
    const float* bqkv = (const float*)d_in[3];
    const float* Wo   = (const float*)d_in[4];
    const float* bo   = (const float*)d_in[5];
    float* out = (float*)d_out;

    float* qkv;
    __nv_bfloat16 *xs, *wqs, *wos, *ys;
    int* lenp;
    cudaGetSymbolAddress((void**)&qkv, g_qkv);
    cudaGetSymbolAddress((void**)&xs,  g_xs);
    cudaGetSymbolAddress((void**)&wqs, g_wqs);
    cudaGetSymbolAddress((void**)&wos, g_wos);
    cudaGetSymbolAddress((void**)&ys,  g_ys);
    cudaGetSymbolAddress((void**)&lenp, g_len);

    cudaFuncSetAttribute(gemm_bf16, cudaFuncAttributeMaxDynamicSharedMemorySize, GEMM_SMEM);

    int nx = M_ * C_, nwq = C3_ * C_, nwo = C_ * C_;
    compute_len<<<B_, 256>>>(am, lenp);
    split_wide<<<nx  / 1024, 256>>>(x,    xs,  C_, 1, nx);
    split_wide<<<nwq / 1024, 256>>>(Wqkv, wqs, C_, 2, nwq);
    split_wide<<<nwo / 1024, 256>>>(Wo,   wos, C_, 2, nwo);

    gemm_bf16<<<dim3(C3_ / 128, M_ / 128), 256, GEMM_SMEM>>>(
        xs, wqs, bqkv, qkv, M_, C3_, KP_);
    flash_attn_tc<<<dim3(T_ / 128, H_, B_), 256>>>(qkv, lenp, ys);
    gemm_bf16<<<dim3(C_ / 128, M_ / 128), 256, GEMM_SMEM>>>(
        ys, wos, bo, out, M_, C_, KP_);
}

// round 5
// speedup vs baseline: 2.1835x; 1.0040x over previous
#include <cuda_runtime.h>
#include <cuda_bf16.h>
#include <cstdint>

// Problem constants
#define B_   4
#define T_   2048
#define C_   1024
#define H_   16
#define HD_  64
#define M_   (B_ * T_)          // 8192
#define C3_  (3 * C_)           // 3072
#define KP_  (3 * C_)           // 3072 concat-K

// tcgen05 only if the device pass has full sm_103a features
#if !defined(__CUDA_ARCH__) || defined(__CUDA_ARCH_FEAT_SM103_ALL)
#define TC_OK 1
#else
#define TC_OK 0
#endif

// ---------------------------------------------------------------------------
// Scratch
// ---------------------------------------------------------------------------
__device__ float g_qkv[(size_t)M_ * C3_];
__device__ __nv_bfloat16 g_xs [(size_t)M_  * KP_];
__device__ __nv_bfloat16 g_wqs[(size_t)C3_ * KP_];
__device__ __nv_bfloat16 g_wos[(size_t)C_  * KP_];
__device__ __nv_bfloat16 g_ys [(size_t)M_  * KP_];
__device__ int g_len[B_];

// ---------------------------------------------------------------------------
// Helpers
// ---------------------------------------------------------------------------
__device__ __forceinline__ uint32_t smem_u32(const void* p) {
    uint32_t a;
    asm("{ .reg .u64 t; cvta.to.shared.u64 t, %1; cvt.u32.u64 %0, t; }"
        : "=r"(a) : "l"(p));
    return a;
}

#define MMA16816(C, A, b0, b1)                                                \
    asm volatile(                                                             \
        "mma.sync.aligned.m16n8k16.row.col.f32.bf16.bf16.f32 "                \
        "{%0,%1,%2,%3},{%4,%5,%6,%7},{%8,%9},{%0,%1,%2,%3};"                  \
        : "+f"((C)[0]), "+f"((C)[1]), "+f"((C)[2]), "+f"((C)[3])              \
        : "r"((A)[0]), "r"((A)[1]), "r"((A)[2]), "r"((A)[3]),                 \
          "r"(b0), "r"(b1))

#define LDSM_X4(R, addr)                                                      \
    asm volatile("ldmatrix.sync.aligned.m8n8.x4.shared.b16 {%0,%1,%2,%3}, [%4];" \
        : "=r"((R)[0]), "=r"((R)[1]), "=r"((R)[2]), "=r"((R)[3]) : "r"(addr))

#define LDSM_X2(r0, r1, addr)                                                 \
    asm volatile("ldmatrix.sync.aligned.m8n8.x2.shared.b16 {%0,%1}, [%2];"    \
        : "=r"(r0), "=r"(r1) : "r"(addr))

#define LDSM_X2T(r0, r1, addr)                                                \
    asm volatile("ldmatrix.sync.aligned.m8n8.x2.trans.shared.b16 {%0,%1}, [%2];" \
        : "=r"(r0), "=r"(r1) : "r"(addr))

__device__ __forceinline__ uint32_t pack_hi(float a, float b) {
    __nv_bfloat162 v = __floats2bfloat162_rn(a, b);
    return *reinterpret_cast<uint32_t*>(&v);
}
__device__ __forceinline__ uint32_t pack_res(float a, float b, uint32_t hp) {
    __nv_bfloat162 h = *reinterpret_cast<__nv_bfloat162*>(&hp);
    __nv_bfloat162 v = __floats2bfloat162_rn(a - __bfloat162float(h.x),
                                             b - __bfloat162float(h.y));
    return *reinterpret_cast<uint32_t*>(&v);
}

#if TC_OK
__device__ __forceinline__ uint32_t elect_one() {
    uint32_t p;
    asm volatile("{ .reg .pred p; elect.sync _|p, 0xFFFFFFFF; selp.b32 %0, 1, 0, p; }"
                 : "=r"(p));
    return p;
}
#define TC_ALLOC(smem_addr, n)  asm volatile("tcgen05.alloc.cta_group::1.sync.aligned.shared::cta.b32 [%0], %1;" :: "r"(smem_addr), "r"(n) : "memory")
#define TC_DEALLOC(tmem, n)     asm volatile("tcgen05.dealloc.cta_group::1.sync.aligned.b32 %0, %1;" :: "r"(tmem), "r"(n))
#define TC_COMMIT(mbar)         asm volatile("tcgen05.commit.cta_group::1.mbarrier::arrive::one.shared::cluster.b64 [%0];" :: "r"(mbar) : "memory")
#define TC_FENCE_AFTER()        asm volatile("tcgen05.fence::after_thread_sync;" ::: "memory")
#define TC_FENCE_BEFORE()       asm volatile("tcgen05.fence::before_thread_sync;" ::: "memory")
#define TC_WAIT_LD()            asm volatile("tcgen05.wait::ld.sync.aligned;" ::: "memory")
#define MBAR_INIT(mbar, cnt)    asm volatile("mbarrier.init.shared.b64 [%0], %1;" :: "r"(mbar), "r"(cnt) : "memory")
#define FENCE_ASYNC_SHARED()    asm volatile("fence.proxy.async.shared::cta;" ::: "memory")
#define MBAR_WAIT(mbar, parity) do {                                          \
    uint32_t _m = (mbar), _p = (parity), _d;                                  \
    asm volatile("{ .reg .pred p; mbarrier.try_wait.parity.acquire.cta.shared::cta.b64 p, [%1], %2; selp.b32 %0, 1, 0, p; }" \
                 : "=r"(_d) : "r"(_m), "r"(_p) : "memory");                   \
    if (!_d) {                                                                \
        asm volatile("{ .reg .pred P1; WL_%=:\n\t"                            \
            "mbarrier.try_wait.parity.acquire.cta.shared::cta.b64 P1, [%0], %1, 0x989680;\n\t" \
            "@P1 bra.uni WD_%=; bra.uni WL_%=; WD_%=: }"                      \
            :: "r"(_m), "r"(_p) : "memory");                                  \
    }                                                                          \
} while (0)
__device__ __forceinline__ void tc_mma_f16_ss(
    uint32_t d_tmem, uint64_t a_desc, uint64_t b_desc, uint32_t idesc, uint32_t en)
{
    asm volatile(
        "{ .reg .pred p; setp.ne.u32 p, %5, 0;\n\t"
        "tcgen05.mma.cta_group::1.kind::f16 [%0], %1, %2, %3, {%4, %4, %4, %4}, p; }"
        :: "r"(d_tmem), "l"(a_desc), "l"(b_desc), "r"(idesc), "r"(0u), "r"(en)
        : "memory");
}
__device__ __forceinline__ void tc_ld_x32(uint32_t* r, uint32_t ta) {
    asm volatile(
        "tcgen05.ld.sync.aligned.32x32b.x32.b32 "
        "{%0,%1,%2,%3,%4,%5,%6,%7,%8,%9,%10,%11,%12,%13,%14,%15,"
        "%16,%17,%18,%19,%20,%21,%22,%23,%24,%25,%26,%27,%28,%29,%30,%31}, [%32];"
        : "=r"(r[0]), "=r"(r[1]), "=r"(r[2]), "=r"(r[3]), "=r"(r[4]), "=r"(r[5]),
          "=r"(r[6]), "=r"(r[7]), "=r"(r[8]), "=r"(r[9]), "=r"(r[10]), "=r"(r[11]),
          "=r"(r[12]), "=r"(r[13]), "=r"(r[14]), "=r"(r[15]), "=r"(r[16]), "=r"(r[17]),
          "=r"(r[18]), "=r"(r[19]), "=r"(r[20]), "=r"(r[21]), "=r"(r[22]), "=r"(r[23]),
          "=r"(r[24]), "=r"(r[25]), "=r"(r[26]), "=r"(r[27]), "=r"(r[28]), "=r"(r[29]),
          "=r"(r[30]), "=r"(r[31])
        : "r"(ta));
}
#define DESC_BASE ((2ull << 61) | (1ull << 46) | (64ull << 32) | (1ull << 16))
#define MK_DESC(a) (DESC_BASE | ((uint64_t)((a) >> 4) & 0x3FFF))
#define SWZ(o) ((o) ^ (((o) >> 3) & 0x70))
#define IDESC ((1u << 4) | (1u << 7) | (1u << 10) | (16u << 17) | (8u << 24))
#endif // TC_OK

// ---------------------------------------------------------------------------
// GEMM: Cout[M,N] = A[M,Kp] @ W[N,Kp]^T + bias
// Fallback (active) path: HMMA, 3-stage cp.async pipeline, 2 CTAs/SM.
// ---------------------------------------------------------------------------
#define TILE_B     16384
#define STAGE_B    (2 * TILE_B)
#define GEMM_SMEM  (1024 + 2 * STAGE_B)   // request covers both paths
#define FB_STAGE_B 20480                  // fallback: (128+128) rows x 40 bf16 x 2B

__global__ __launch_bounds__(256, 2) void gemm_bf16(
    const __nv_bfloat16* __restrict__ A, const __nv_bfloat16* __restrict__ W,
    const float* __restrict__ bias, float* __restrict__ Cout,
    int M, int N, int Kp)
{
    extern __shared__ char sm[];
    const int tid = threadIdx.x;
    const int bm = blockIdx.y * 128;
    const int bn = blockIdx.x * 128;

#if TC_OK
    const uint32_t smb = smem_u32(sm);
    if (tid < 32) TC_ALLOC(smb, 128);
    if (tid == 0) { MBAR_INIT(smb + 8, 1); MBAR_INIT(smb + 16, 1); }
    __syncthreads();
    uint32_t tmem;
    asm volatile("ld.shared.b32 %0, [%1];" : "=r"(tmem) : "r"(smb));

    const int nk = Kp >> 6;
    auto load_chunk = [&](int c, int p) {
        const int k0 = c << 6;
        char* bufp = sm + 1024 + p * STAGE_B;
        #pragma unroll
        for (int t = 0; t < 4; t++) {
            int e = tid + t * 256;
            int r = e >> 3, c16 = e & 7;
            uint4 v = *(const uint4*)(A + (size_t)(bm + r) * Kp + k0 + c16 * 8);
            *(uint4*)(bufp + SWZ(r * 128 + c16 * 16)) = v;
        }
        #pragma unroll
        for (int t = 0; t < 4; t++) {
            int e = tid + t * 256;
            int r = e >> 3, c16 = e & 7;
            uint4 v = *(const uint4*)(W + (size_t)(bn + r) * Kp + k0 + c16 * 8);
            *(uint4*)(bufp + TILE_B + SWZ(r * 128 + c16 * 16)) = v;
        }
        FENCE_ASYNC_SHARED();
    };
    load_chunk(0, 0);
    __syncthreads();
    for (int c = 0; c < nk; c++) {
        const int p = c & 1;
        if (tid < 32 && elect_one()) {
            uint32_t base = smb + 1024 + p * STAGE_B;
            uint64_t ad = MK_DESC(base);
            uint64_t bd = MK_DESC(base + TILE_B);
            #pragma unroll
            for (int ks = 0; ks < 4; ks++)
                tc_mma_f16_ss(tmem, ad + ks * 2, bd + ks * 2, IDESC,
                              (uint32_t)((c > 0) | (ks > 0)));
            TC_COMMIT(smb + 8 + 8 * p);
        }
        if (c + 1 < nk) {
            if (c >= 1) MBAR_WAIT(smb + 8 + 8 * ((c - 1) & 1), ((c - 1) >> 1) & 1);
            load_chunk(c + 1, p ^ 1);
        }
        __syncthreads();
    }
    MBAR_WAIT(smb + 8 + 8 * ((nk - 1) & 1), ((nk - 1) >> 1) & 1);
    TC_FENCE_AFTER();
    if (tid < 128) {
        const int row = bm + tid;
        #pragma unroll
        for (int cb = 0; cb < 4; cb++) {
            uint32_t d[32];
            tc_ld_x32(d, tmem + cb * 32);
            TC_WAIT_LD();
            float* op = Cout + (size_t)row * N + bn + cb * 32;
            const float* bp = bias + bn + cb * 32;
            #pragma unroll
            for (int j = 0; j < 32; j += 4) {
                float4 r;
                r.x = __uint_as_float(d[j + 0]) + bp[j + 0];
                r.y = __uint_as_float(d[j + 1]) + bp[j + 1];
                r.z = __uint_as_float(d[j + 2]) + bp[j + 2];
                r.w = __uint_as_float(d[j + 3]) + bp[j + 3];
                *(float4*)(op + j) = r;
            }
        }
        TC_FENCE_BEFORE();
    }
    __syncthreads();
    if (tid < 32) TC_DEALLOC(tmem, 128);
#else
    // ================= HMMA fallback: 3-stage pipeline =================
    const int warp = tid >> 5, lane = tid & 31;
    const int moff = (warp >> 1) * 32;    // 4 warps over M
    const int noff = (warp & 1) * 64;     // 2 warps over N

    float acc[2][8][4];
    #pragma unroll
    for (int a = 0; a < 2; a++)
        #pragma unroll
        for (int b = 0; b < 8; b++)
            #pragma unroll
            for (int c = 0; c < 4; c++) acc[a][b][c] = 0.f;

    auto issue_loads = [&](int c, int s) {
        const int k0 = c * 32;
        __nv_bfloat16* dstA = (__nv_bfloat16*)(sm + s * FB_STAGE_B);
        __nv_bfloat16* dstB = dstA + 5120;
        #pragma unroll
        for (int t = 0; t < 2; t++) {
            int idx = tid + t * 256;               // 0..511
            int r = idx >> 2, c16 = idx & 3;
            uint32_t da = smem_u32(dstA + r * 40 + c16 * 8);
            const void* ga = A + (size_t)(bm + r) * Kp + k0 + c16 * 8;
            asm volatile("cp.async.cg.shared.global [%0], [%1], 16;"
                         :: "r"(da), "l"(ga) : "memory");
            uint32_t db = smem_u32(dstB + r * 40 + c16 * 8);
            const void* gb = W + (size_t)(bn + r) * Kp + k0 + c16 * 8;
            asm volatile("cp.async.cg.shared.global [%0], [%1], 16;"
                         :: "r"(db), "l"(gb) : "memory");
        }
    };

    const int nk = Kp >> 5;   // >= 96 here
    issue_loads(0, 0);
    asm volatile("cp.async.commit_group;" ::: "memory");
    issue_loads(1, 1);
    asm volatile("cp.async.commit_group;" ::: "memory");

    int s_next = 2;   // stage index of chunk c+2
    for (int c = 0; c < nk; c++) {
        asm volatile("cp.async.wait_group 1;" ::: "memory");
        __syncthreads();
        if (c + 2 < nk) issue_loads(c + 2, s_next);
        asm volatile("cp.async.commit_group;" ::: "memory");

        const int s_cur = (s_next + 1 >= 3) ? s_next + 1 - 3 : s_next + 1; // (c)%3
        const __nv_bfloat16* pA = (const __nv_bfloat16*)(sm + s_cur * FB_STAGE_B);
        const __nv_bfloat16* pB = pA + 5120;
        #pragma unroll
        for (int kh = 0; kh < 32; kh += 16) {
            uint32_t av[2][4];
            #pragma unroll
            for (int mb = 0; mb < 2; mb++) {
                int row = moff + mb * 16 + (lane & 7) + 8 * ((lane >> 3) & 1);
                int col = kh + 8 * (lane >> 4);
                LDSM_X4(av[mb], smem_u32(pA + row * 40 + col));
            }
            #pragma unroll
            for (int nb = 0; nb < 8; nb++) {
                int row = noff + nb * 8 + (lane & 7);
                int col = kh + 8 * ((lane >> 3) & 1);
                uint32_t b0, b1;
                LDSM_X2(b0, b1, smem_u32(pB + row * 40 + col));
                #pragma unroll
                for (int mb = 0; mb < 2; mb++)
                    MMA16816(acc[mb][nb], av[mb], b0, b1);
            }
        }
        s_next = (s_next + 1 >= 3) ? s_next + 1 - 3 : s_next + 1;
    }

    const int r0 = lane >> 2, c0 = (lane & 3) * 2;
    #pragma unroll
    for (int mb = 0; mb < 2; mb++)
        #pragma unroll
        for (int nb = 0; nb < 8; nb++) {
            int row = bm + moff + mb * 16 + r0;
            int col = bn + noff + nb * 8 + c0;
            float2 v0 = make_float2(acc[mb][nb][0] + bias[col],
                                    acc[mb][nb][1] + bias[col + 1]);
            *(float2*)(Cout + (size_t)row * N + col) = v0;
            float2 v1 = make_float2(acc[mb][nb][2] + bias[col],
                                    acc[mb][nb][3] + bias[col + 1]);
            *(float2*)(Cout + (size_t)(row + 8) * N + col) = v1;
        }
#endif
}

// ---------------------------------------------------------------------------
// per-batch valid length
// ---------------------------------------------------------------------------
__global__ void compute_len(const int* __restrict__ am, int* __restrict__ out) {
    __shared__ int red[8];
    int b = blockIdx.x, acc = 0;
    for (int i = threadIdx.x; i < T_; i += 256) acc += am[b * T_ + i];
    #pragma unroll
    for (int o = 16; o; o >>= 1) acc += __shfl_xor_sync(0xffffffffu, acc, o);
    if ((threadIdx.x & 31) == 0) red[threadIdx.x >> 5] = acc;
    __syncthreads();
    if (threadIdx.x == 0) {
        int v = 0;
        #pragma unroll
        for (int i = 0; i < 8; i++) v += red[i];
        out[b] = v;
    }
}

// ---------------------------------------------------------------------------
// fp32 [R,K] -> bf16 wide [R,3K]
// ---------------------------------------------------------------------------
__global__ __launch_bounds__(256) void split_wide(
    const float* __restrict__ src, __nv_bfloat16* __restrict__ dst,
    int K, int lo_seg, int n)
{
    int i = (blockIdx.x * 256 + threadIdx.x) * 4;
    if (i >= n) return;
    int r = i / K, j = i % K;
    float4 v = *(const float4*)(src + i);
    float f[4] = {v.x, v.y, v.z, v.w};
    size_t base = (size_t)r * 3 * K + j;
    size_t off_l = (lo_seg == 1) ? K : 2 * (size_t)K;
    size_t off_h2 = (lo_seg == 1) ? 2 * (size_t)K : K;
    #pragma unroll
    for (int q = 0; q < 4; q++) {
        __nv_bfloat16 h = __float2bfloat16(f[q]);
        __nv_bfloat16 l = __float2bfloat16(f[q] - __bfloat162float(h));
        dst[base + q] = h;
        dst[base + off_h2 + q] = h;
        dst[base + off_l + q] = l;
    }
}

// ---------------------------------------------------------------------------
// Tensor-core flash attention (unchanged from Round 4)
// ---------------------------------------------------------------------------
#define PITCH 72

__global__ __launch_bounds__(256, 1) void flash_attn_tc(
    const float* __restrict__ qkv, const int* __restrict__ lenp,
    __nv_bfloat16* __restrict__ ys)
{
    __shared__ __nv_bfloat16 sbuf[4 * 64 * PITCH];
    __nv_bfloat16* Kh = sbuf;
    __nv_bfloat16* Kl = sbuf + 64 * PITCH;
    __nv_bfloat16* Vh = sbuf + 2 * 64 * PITCH;
    __nv_bfloat16* Vl = sbuf + 3 * 64 * PITCH;
    __nv_bfloat16* Qh = sbuf;
    __nv_bfloat16* Ql = sbuf + 128 * PITCH;

    const int b = blockIdx.z, h = blockIdx.y, qt = blockIdx.x;
    const int q0 = qt * 128;
    const int tid = threadIdx.x;
    const int warp = tid >> 5, lane = tid & 31;
    const int len = lenp[b];
    const float* base = qkv + (size_t)b * T_ * C3_ + h * HD_;

    #pragma unroll
    for (int t = 0; t < 8; t++) {
        int e = tid + t * 256;
        int r = e >> 4, c4 = e & 15;
        float4 v = *(const float4*)(base + (size_t)(q0 + r) * C3_ + c4 * 4);
        float f[4] = {v.x, v.y, v.z, v.w};
        #pragma unroll
        for (int j = 0; j < 4; j++) {
            __nv_bfloat16 hi = __float2bfloat16(f[j]);
            Qh[r * PITCH + c4 * 4 + j] = hi;
            Ql[r * PITCH + c4 * 4 + j] = __float2bfloat16(f[j] - __bfloat162float(hi));
        }
    }
    __syncthreads();

    uint32_t qh[4][4], ql[4][4];
    {
        int row = warp * 16 + (lane & 7) + 8 * ((lane >> 3) & 1);
        #pragma unroll
        for (int ks = 0; ks < 4; ks++) {
            int col = ks * 16 + 8 * (lane >> 4);
            LDSM_X4(qh[ks], smem_u32(Qh + row * PITCH + col));
            LDSM_X4(ql[ks], smem_u32(Ql + row * PITCH + col));
        }
    }
    __syncthreads();

    float m_[2] = {-1e30f, -1e30f}, l_[2] = {0.f, 0.f};
    float O[8][4] = {};

    const int kt_len = (len + 63) >> 6;
    const int kt_max = min(2 * qt + 1, kt_len - 1);
    const int wrow_max = q0 + warp * 16 + 15;
    const int r0 = lane >> 2, cb = (lane & 3) * 2;
    const int row0 = q0 + warp * 16 + r0, row1 = row0 + 8;

    for (int kt = 0; kt <= kt_max; kt++) {
        const int k0 = kt * 64;
        __syncthreads();
        #pragma unroll
        for (int t = 0; t < 4; t++) {
            int e = tid + t * 256;
            int r = e >> 4, c4 = e & 15;
            float4 kv = *(const float4*)(base + C_ + (size_t)(k0 + r) * C3_ + c4 * 4);
            float4 vv = *(const float4*)(base + 2 * C_ + (size_t)(k0 + r) * C3_ + c4 * 4);
            float fk[4] = {kv.x, kv.y, kv.z, kv.w};
            float fv[4] = {vv.x, vv.y, vv.z, vv.w};
            #pragma unroll
            for (int j = 0; j < 4; j++) {
                __nv_bfloat16 hk = __float2bfloat16(fk[j]);
                Kh[r * PITCH + c4 * 4 + j] = hk;
                Kl[r * PITCH + c4 * 4 + j] = __float2bfloat16(fk[j] - __bfloat162float(hk));
                __nv_bfloat16 hv = __float2bfloat16(fv[j]);
                Vh[r * PITCH + c4 * 4 + j] = hv;
                Vl[r * PITCH + c4 * 4 + j] = __float2bfloat16(fv[j] - __bfloat162float(hv));
            }
        }
        __syncthreads();
        if (k0 > wrow_max) continue;

        float S[8][4] = {};
        {
            int krow = (lane & 7);
            int kcol8 = 8 * ((lane >> 3) & 1);
            #pragma unroll
            for (int nb = 0; nb < 8; nb++) {
                #pragma unroll
                for (int ks = 0; ks < 4; ks++) {
                    uint32_t bh0, bh1, bl0, bl1;
                    uint32_t ah = smem_u32(Kh + (nb * 8 + krow) * PITCH + ks * 16 + kcol8);
                    uint32_t al = smem_u32(Kl + (nb * 8 + krow) * PITCH + ks * 16 + kcol8);
                    LDSM_X2(bh0, bh1, ah);
                    LDSM_X2(bl0, bl1, al);
                    MMA16816(S[nb], qh[ks], bh0, bh1);
                    MMA16816(S[nb], ql[ks], bh0, bh1);
                    MMA16816(S[nb], qh[ks], bl0, bl1);
                }
            }
        }

        float ml0 = -1e30f, ml1 = -1e30f;
        #pragma unroll
        for (int nb = 0; nb < 8; nb++) {
            int c0 = k0 + nb * 8 + cb;
            S[nb][0] = (c0     <= row0 && c0     < len) ? S[nb][0] * 0.125f : -1e30f;
            S[nb][1] = (c0 + 1 <= row0 && c0 + 1 < len) ? S[nb][1] * 0.125f : -1e30f;
            S[nb][2] = (c0     <= row1 && c0     < len) ? S[nb][2] * 0.125f : -1e30f;
            S[nb][3] = (c0 + 1 <= row1 && c0 + 1 < len) ? S[nb][3] * 0.125f : -1e30f;
            ml0 = fmaxf(ml0, fmaxf(S[nb][0], S[nb][1]));
            ml1 = fmaxf(ml1, fmaxf(S[nb][2], S[nb][3]));
        }
        ml0 = fmaxf(ml0, __shfl_xor_sync(0xffffffffu, ml0, 1));
        ml0 = fmaxf(ml0, __shfl_xor_sync(0xffffffffu, ml0, 2));
        ml1 = fmaxf(ml1, __shfl_xor_sync(0xffffffffu, ml1, 1));
        ml1 = fmaxf(ml1, __shfl_xor_sync(0xffffffffu, ml1, 2));
        float mn0 = fmaxf(m_[0], ml0), mn1 = fmaxf(m_[1], ml1);
        float corr0 = __expf(m_[0] - mn0), corr1 = __expf(m_[1] - mn1);
        float ls0 = 0.f, ls1 = 0.f;
        #pragma unroll
        for (int nb = 0; nb < 8; nb++) {
            S[nb][0] = __expf(S[nb][0] - mn0); ls0 += S[nb][0];
            S[nb][1] = __expf(S[nb][1] - mn0); ls0 += S[nb][1];
            S[nb][2] = __expf(S[nb][2] - mn1); ls1 += S[nb][2];
            S[nb][3] = __expf(S[nb][3] - mn1); ls1 += S[nb][3];
        }
        ls0 += __shfl_xor_sync(0xffffffffu, ls0, 1);
        ls0 += __shfl_xor_sync(0xffffffffu, ls0, 2);
        ls1 += __shfl_xor_sync(0xffffffffu, ls1, 1);
        ls1 += __shfl_xor_sync(0xffffffffu, ls1, 2);
        l_[0] = l_[0] * corr0 + ls0;
        l_[1] = l_[1] * corr1 + ls1;
        m_[0] = mn0; m_[1] = mn1;
        #pragma unroll
        for (int nb = 0; nb < 8; nb++) {
            O[nb][0] *= corr0; O[nb][1] *= corr0;
            O[nb][2] *= corr1; O[nb][3] *= corr1;
        }

        {
            int vrow8 = (lane & 7) + 8 * ((lane >> 3) & 1);
            #pragma unroll
            for (int ks = 0; ks < 4; ks++) {
                uint32_t ph[4], pl[4];
                ph[0] = pack_hi(S[2 * ks][0], S[2 * ks][1]);
                ph[1] = pack_hi(S[2 * ks][2], S[2 * ks][3]);
                ph[2] = pack_hi(S[2 * ks + 1][0], S[2 * ks + 1][1]);
                ph[3] = pack_hi(S[2 * ks + 1][2], S[2 * ks + 1][3]);
                pl[0] = pack_res(S[2 * ks][0], S[2 * ks][1], ph[0]);
                pl[1] = pack_res(S[2 * ks][2], S[2 * ks][3], ph[1]);
                pl[2] = pack_res(S[2 * ks + 1][0], S[2 * ks + 1][1], ph[2]);
                pl[3] = pack_res(S[2 * ks + 1][2], S[2 * ks + 1][3], ph[3]);
                #pragma unroll
                for (int nb = 0; nb < 8; nb++) {
                    uint32_t vh0, vh1, vl0, vl1;
                    uint32_t av = smem_u32(Vh + (ks * 16 + vrow8) * PITCH + nb * 8);
                    uint32_t al = smem_u32(Vl + (ks * 16 + vrow8) * PITCH + nb * 8);
                    LDSM_X2T(vh0, vh1, av);
                    LDSM_X2T(vl0, vl1, al);
                    MMA16816(O[nb], ph, vh0, vh1);
                    MMA16816(O[nb], pl, vh0, vh1);
                    MMA16816(O[nb], ph, vl0, vl1);
                }
            }
        }
    }

    float inv0 = (row0 < len && l_[0] > 0.f) ? (1.f / l_[0]) : 0.f;
    float inv1 = (row1 < len && l_[1] > 0.f) ? (1.f / l_[1]) : 0.f;
    size_t rb0 = ((size_t)b * T_ + row0) * KP_;
    size_t rb1 = ((size_t)b * T_ + row1) * KP_;
    #pragma unroll
    for (int nb = 0; nb < 8; nb++) {
        int hcol = h * HD_ + nb * 8 + cb;
        uint32_t h0 = pack_hi(O[nb][0] * inv0, O[nb][1] * inv0);
        uint32_t l0 = pack_res(O[nb][0] * inv0, O[nb][1] * inv0, h0);
        uint32_t h1 = pack_hi(O[nb][2] * inv1, O[nb][3] * inv1);
        uint32_t l1 = pack_res(O[nb][2] * inv1, O[nb][3] * inv1, h1);
        *(uint32_t*)(ys + rb0 + hcol)          = h0;
        *(uint32_t*)(ys + rb0 + C_ + hcol)     = l0;
        *(uint32_t*)(ys + rb0 + 2 * C_ + hcol) = h0;
        *(uint32_t*)(ys + rb1 + hcol)          = h1;
        *(uint32_t*)(ys + rb1 + C_ + hcol)     = l1;
        *(uint32_t*)(ys + rb1 + 2 * C_ + hcol) = h1;
    }
}

// ---------------------------------------------------------------------------
extern "C" void kernel_launch(void* const* d_in, const int* in_sizes, int n_in,
                              void* d_out, int out_size)
{
    const float* x    = (const float*)d_in[0];
    const int*   am   = (const int*)  d_in[1];
    const float* Wqkv = (const float*)d_in[2];
    const float* bqkv = (const float*)d_in[3];
    const float* Wo   = (const float*)d_in[4];
    const float* bo   = (const float*)d_in[5];
    float* out = (float*)d_out;

    float* qkv;
    __nv_bfloat16 *xs, *wqs, *wos, *ys;
    int* lenp;
    cudaGetSymbolAddress((void**)&qkv, g_qkv);
    cudaGetSymbolAddress((void**)&xs,  g_xs);
    cudaGetSymbolAddress((void**)&wqs, g_wqs);
    cudaGetSymbolAddress((void**)&wos, g_wos);
    cudaGetSymbolAddress((void**)&ys,  g_ys);
    cudaGetSymbolAddress((void**)&lenp, g_len);

    cudaFuncSetAttribute(gemm_bf16, cudaFuncAttributeMaxDynamicSharedMemorySize, GEMM_SMEM);

    int nx = M_ * C_, nwq = C3_ * C_, nwo = C_ * C_;
    compute_len<<<B_, 256>>>(am, lenp);
    split_wide<<<nx  / 1024, 256>>>(x,    xs,  C_, 1, nx);
    split_wide<<<nwq / 1024, 256>>>(Wqkv, wqs, C_, 2, nwq);
    split_wide<<<nwo / 1024, 256>>>(Wo,   wos, C_, 2, nwo);

    gemm_bf16<<<dim3(C3_ / 128, M_ / 128), 256, GEMM_SMEM>>>(
        xs, wqs, bqkv, qkv, M_, C3_, KP_);
    flash_attn_tc<<<dim3(T_ / 128, H_, B_), 256>>>(qkv, lenp, ys);
    gemm_bf16<<<dim3(C_ / 128, M_ / 128), 256, GEMM_SMEM>>>(
        ys, wos, bo, out, M_, C_, KP_);
}

// round 6
// speedup vs baseline: 2.1940x; 1.0048x over previous
#include <cuda_runtime.h>
#include <cuda_bf16.h>
#include <cstdint>

// Problem constants
#define B_   4
#define T_   2048
#define C_   1024
#define H_   16
#define HD_  64
#define M_   (B_ * T_)          // 8192
#define C3_  (3 * C_)           // 3072

// ---------------------------------------------------------------------------
// Scratch (device globals)
// ---------------------------------------------------------------------------
__device__ float g_qkv[(size_t)M_ * C3_];
__device__ __nv_bfloat16 g_xh [(size_t)M_  * C_], g_xl [(size_t)M_  * C_];
__device__ __nv_bfloat16 g_wqh[(size_t)C3_ * C_], g_wql[(size_t)C3_ * C_];
__device__ __nv_bfloat16 g_woh[(size_t)C_  * C_], g_wol[(size_t)C_  * C_];
__device__ __nv_bfloat16 g_yh [(size_t)M_  * C_], g_yl [(size_t)M_  * C_];
__device__ int g_len[B_];

// ---------------------------------------------------------------------------
// Helpers
// ---------------------------------------------------------------------------
__device__ __forceinline__ uint32_t smem_u32(const void* p) {
    uint32_t a;
    asm("{ .reg .u64 t; cvta.to.shared.u64 t, %1; cvt.u32.u64 %0, t; }"
        : "=r"(a) : "l"(p));
    return a;
}

#define MMA16816(C, A, b0, b1)                                                \
    asm volatile(                                                             \
        "mma.sync.aligned.m16n8k16.row.col.f32.bf16.bf16.f32 "                \
        "{%0,%1,%2,%3},{%4,%5,%6,%7},{%8,%9},{%0,%1,%2,%3};"                  \
        : "+f"((C)[0]), "+f"((C)[1]), "+f"((C)[2]), "+f"((C)[3])              \
        : "r"((A)[0]), "r"((A)[1]), "r"((A)[2]), "r"((A)[3]),                 \
          "r"(b0), "r"(b1))

#define LDSM_X4(R, addr)                                                      \
    asm volatile("ldmatrix.sync.aligned.m8n8.x4.shared.b16 {%0,%1,%2,%3}, [%4];" \
        : "=r"((R)[0]), "=r"((R)[1]), "=r"((R)[2]), "=r"((R)[3]) : "r"(addr))

#define LDSM_X2(r0, r1, addr)                                                 \
    asm volatile("ldmatrix.sync.aligned.m8n8.x2.shared.b16 {%0,%1}, [%2];"    \
        : "=r"(r0), "=r"(r1) : "r"(addr))

#define LDSM_X2T(r0, r1, addr)                                                \
    asm volatile("ldmatrix.sync.aligned.m8n8.x2.trans.shared.b16 {%0,%1}, [%2];" \
        : "=r"(r0), "=r"(r1) : "r"(addr))

#define CP_ASYNC16(dst, src)                                                  \
    asm volatile("cp.async.cg.shared.global [%0], [%1], 16;"                  \
                 :: "r"(dst), "l"(src) : "memory")
#define CP_COMMIT() asm volatile("cp.async.commit_group;" ::: "memory")
#define CP_WAIT0()  asm volatile("cp.async.wait_group 0;" ::: "memory")
#define CP_WAIT1()  asm volatile("cp.async.wait_group 1;" ::: "memory")

__device__ __forceinline__ uint32_t pack_hi(float a, float b) {
    __nv_bfloat162 v = __floats2bfloat162_rn(a, b);
    return *reinterpret_cast<uint32_t*>(&v);
}
__device__ __forceinline__ uint32_t pack_res(float a, float b, uint32_t hp) {
    __nv_bfloat162 h = *reinterpret_cast<__nv_bfloat162*>(&hp);
    __nv_bfloat162 v = __floats2bfloat162_rn(a - __bfloat162float(h.x),
                                             b - __bfloat162float(h.y));
    return *reinterpret_cast<uint32_t*>(&v);
}

// ---------------------------------------------------------------------------
// HMMA GEMM: Cout[M,N] = (Ah+Al)[M,K] @ (Wh+Wl)[N,K]^T + bias
// 128x128 tile, k-chunk 16, 3-stage cp.async pipeline, 2 CTAs/SM.
// Stage: Ah|Al|Wh|Wl, each 128 rows x 24 bf16 (pitch 24 = conflict-free LDSM).
// ---------------------------------------------------------------------------
#define GTILE_B    6144                    // 128*24*2
#define GSTAGE_B   (4 * GTILE_B)           // 24576
#define GEMM_SMEM  (3 * GSTAGE_B)          // 73728

__global__ __launch_bounds__(256, 2) void gemm_bf16(
    const __nv_bfloat16* __restrict__ Ah, const __nv_bfloat16* __restrict__ Al,
    const __nv_bfloat16* __restrict__ Wh, const __nv_bfloat16* __restrict__ Wl,
    const float* __restrict__ bias, float* __restrict__ Cout,
    int M, int N, int K)
{
    extern __shared__ char sm[];
    const int tid = threadIdx.x;
    const int bm = blockIdx.y * 128;
    const int bn = blockIdx.x * 128;
    const int warp = tid >> 5, lane = tid & 31;
    const int moff = (warp >> 1) * 32;     // 4 warps over M
    const int noff = (warp & 1) * 64;      // 2 warps over N

    float acc[2][8][4];
    #pragma unroll
    for (int a = 0; a < 2; a++)
        #pragma unroll
        for (int b = 0; b < 8; b++)
            #pragma unroll
            for (int c = 0; c < 4; c++) acc[a][b][c] = 0.f;

    const int r_ld = tid >> 1, half8 = (tid & 1) * 8;   // one 16B chunk per tile
    auto issue = [&](int c, int s) {
        const int k0 = c << 4;
        char* st = sm + s * GSTAGE_B;
        uint32_t d = smem_u32(st + (r_ld * 24 + half8) * 2);
        CP_ASYNC16(d,              Ah + (size_t)(bm + r_ld) * K + k0 + half8);
        CP_ASYNC16(d + GTILE_B,    Al + (size_t)(bm + r_ld) * K + k0 + half8);
        CP_ASYNC16(d + 2 * GTILE_B, Wh + (size_t)(bn + r_ld) * K + k0 + half8);
        CP_ASYNC16(d + 3 * GTILE_B, Wl + (size_t)(bn + r_ld) * K + k0 + half8);
        CP_COMMIT();
    };

    const int nk = K >> 4;                 // 64
    issue(0, 0);
    issue(1, 1);

    const int arow = moff + (lane & 7) + 8 * ((lane >> 3) & 1);
    const int acol = 8 * (lane >> 4);
    const int wrow_l = (lane & 7);
    const int wcol = 8 * ((lane >> 3) & 1);

    int s = 0;
    for (int c = 0; c < nk; c++) {
        CP_WAIT1();
        __syncthreads();
        if (c + 2 < nk) issue(c + 2, (s + 2 >= 3) ? s - 1 : s + 2);
        else CP_COMMIT();

        char* st = sm + s * GSTAGE_B;
        uint32_t ah[2][4], al[2][4];
        #pragma unroll
        for (int mb = 0; mb < 2; mb++) {
            LDSM_X4(ah[mb], smem_u32(st + ((arow + mb * 16) * 24 + acol) * 2));
            LDSM_X4(al[mb], smem_u32(st + GTILE_B + ((arow + mb * 16) * 24 + acol) * 2));
        }
        #pragma unroll
        for (int nb = 0; nb < 8; nb++) {
            int wr = noff + nb * 8 + wrow_l;
            uint32_t bh0, bh1, bl0, bl1;
            LDSM_X2(bh0, bh1, smem_u32(st + 2 * GTILE_B + (wr * 24 + wcol) * 2));
            LDSM_X2(bl0, bl1, smem_u32(st + 3 * GTILE_B + (wr * 24 + wcol) * 2));
            #pragma unroll
            for (int mb = 0; mb < 2; mb++) {
                MMA16816(acc[mb][nb], ah[mb], bh0, bh1);
                MMA16816(acc[mb][nb], al[mb], bh0, bh1);
                MMA16816(acc[mb][nb], ah[mb], bl0, bl1);
            }
        }
        s = (s + 1 >= 3) ? 0 : s + 1;
    }

    const int r0 = lane >> 2, c0 = (lane & 3) * 2;
    #pragma unroll
    for (int mb = 0; mb < 2; mb++)
        #pragma unroll
        for (int nb = 0; nb < 8; nb++) {
            int row = bm + moff + mb * 16 + r0;
            int col = bn + noff + nb * 8 + c0;
            float2 v0 = make_float2(acc[mb][nb][0] + bias[col],
                                    acc[mb][nb][1] + bias[col + 1]);
            *(float2*)(Cout + (size_t)row * N + col) = v0;
            float2 v1 = make_float2(acc[mb][nb][2] + bias[col],
                                    acc[mb][nb][3] + bias[col + 1]);
            *(float2*)(Cout + (size_t)(row + 8) * N + col) = v1;
        }
}

// ---------------------------------------------------------------------------
// per-batch valid length
// ---------------------------------------------------------------------------
__global__ void compute_len(const int* __restrict__ am, int* __restrict__ out) {
    __shared__ int red[8];
    int b = blockIdx.x, acc = 0;
    for (int i = threadIdx.x; i < T_; i += 256) acc += am[b * T_ + i];
    #pragma unroll
    for (int o = 16; o; o >>= 1) acc += __shfl_xor_sync(0xffffffffu, acc, o);
    if ((threadIdx.x & 31) == 0) red[threadIdx.x >> 5] = acc;
    __syncthreads();
    if (threadIdx.x == 0) {
        int v = 0;
        #pragma unroll
        for (int i = 0; i < 8; i++) v += red[i];
        out[b] = v;
    }
}

// ---------------------------------------------------------------------------
// fp32 -> bf16 hi/lo split
// ---------------------------------------------------------------------------
__global__ __launch_bounds__(256) void split_hl(
    const float* __restrict__ s, __nv_bfloat16* __restrict__ h,
    __nv_bfloat16* __restrict__ l, int n)
{
    int i = (blockIdx.x * 256 + threadIdx.x) * 4;
    if (i >= n) return;
    float4 v = *(const float4*)(s + i);
    uint32_t h01 = pack_hi(v.x, v.y), h23 = pack_hi(v.z, v.w);
    uint32_t l01 = pack_res(v.x, v.y, h01), l23 = pack_res(v.z, v.w, h23);
    *(uint32_t*)(h + i) = h01; *(uint32_t*)(h + i + 2) = h23;
    *(uint32_t*)(l + i) = l01; *(uint32_t*)(l + i + 2) = l23;
}

// ---------------------------------------------------------------------------
// Tensor-core flash attention with cp.async double-buffered K/V staging.
// 128 q-rows/CTA, 8 warps x 16 rows, 64-key tiles.
// ---------------------------------------------------------------------------
#define PITCH 72
#define ATTN_BF16_B  (4 * 64 * PITCH * 2)            // 36864
#define ATTN_F32_B   (2 * 2 * 64 * 64 * 4)           // 65536
#define ATTN_SMEM    (ATTN_BF16_B + ATTN_F32_B)      // 102400

__global__ __launch_bounds__(256, 1) void flash_attn_tc(
    const float* __restrict__ qkv, const int* __restrict__ lenp,
    __nv_bfloat16* __restrict__ yh, __nv_bfloat16* __restrict__ yl)
{
    extern __shared__ char smdyn[];
    __nv_bfloat16* Kh = (__nv_bfloat16*)smdyn;
    __nv_bfloat16* Kl = Kh + 64 * PITCH;
    __nv_bfloat16* Vh = Kh + 2 * 64 * PITCH;
    __nv_bfloat16* Vl = Kh + 3 * 64 * PITCH;
    __nv_bfloat16* Qh = Kh;                 // pre-loop staging alias
    __nv_bfloat16* Ql = Kh + 128 * PITCH;
    float* F32 = (float*)(smdyn + ATTN_BF16_B);   // [2][K 4096 | V 4096] floats

    const int b = blockIdx.z, h = blockIdx.y, qt = blockIdx.x;
    const int q0 = qt * 128;
    const int tid = threadIdx.x;
    const int warp = tid >> 5, lane = tid & 31;
    const int len = lenp[b];
    const float* base = qkv + (size_t)b * T_ * C3_ + h * HD_;

    const int kt_len = (len + 63) >> 6;
    const int kt_max = min(2 * qt + 1, kt_len - 1);

    auto issue_kv = [&](int kt, int p) {
        const float* srcK = base + C_     + (size_t)(kt * 64) * C3_;
        const float* srcV = base + 2 * C_ + (size_t)(kt * 64) * C3_;
        float* dstK = F32 + p * 8192;
        float* dstV = dstK + 4096;
        #pragma unroll
        for (int t = 0; t < 4; t++) {
            int e = tid + t * 256;
            int r = e >> 4, c4 = (e & 15) * 4;
            CP_ASYNC16(smem_u32(dstK + r * 64 + c4), srcK + (size_t)r * C3_ + c4);
            CP_ASYNC16(smem_u32(dstV + r * 64 + c4), srcV + (size_t)r * C3_ + c4);
        }
        CP_COMMIT();
    };

    issue_kv(0, 0);   // overlap first K/V fetch with Q staging

    // ---- stage Q fp32 -> hi/lo bf16 ----
    #pragma unroll
    for (int t = 0; t < 8; t++) {
        int e = tid + t * 256;
        int r = e >> 4, c4 = (e & 15) * 4;
        float4 v = *(const float4*)(base + (size_t)(q0 + r) * C3_ + c4);
        uint32_t h01 = pack_hi(v.x, v.y), h23 = pack_hi(v.z, v.w);
        *(uint32_t*)(Qh + r * PITCH + c4)     = h01;
        *(uint32_t*)(Qh + r * PITCH + c4 + 2) = h23;
        *(uint32_t*)(Ql + r * PITCH + c4)     = pack_res(v.x, v.y, h01);
        *(uint32_t*)(Ql + r * PITCH + c4 + 2) = pack_res(v.z, v.w, h23);
    }
    __syncthreads();

    uint32_t qh[4][4], ql[4][4];
    {
        int row = warp * 16 + (lane & 7) + 8 * ((lane >> 3) & 1);
        #pragma unroll
        for (int ks = 0; ks < 4; ks++) {
            int col = ks * 16 + 8 * (lane >> 4);
            LDSM_X4(qh[ks], smem_u32(Qh + row * PITCH + col));
            LDSM_X4(ql[ks], smem_u32(Ql + row * PITCH + col));
        }
    }

    float m_[2] = {-1e30f, -1e30f}, l_[2] = {0.f, 0.f};
    float O[8][4] = {};

    const int wrow_max = q0 + warp * 16 + 15;
    const int r0 = lane >> 2, cb = (lane & 3) * 2;
    const int row0 = q0 + warp * 16 + r0, row1 = row0 + 8;

    for (int kt = 0; kt <= kt_max; kt++) {
        const int k0 = kt * 64;
        const int p = kt & 1;
        CP_WAIT0();
        __syncthreads();   // staged f32 ready; prior compute done (incl. Q frags)

        // convert f32 staging -> hi/lo bf16
        {
            const float* Kf = F32 + p * 8192;
            const float* Vf = Kf + 4096;
            #pragma unroll
            for (int t = 0; t < 4; t++) {
                int e = tid + t * 256;
                int r = e >> 4, c4 = (e & 15) * 4;
                float4 kv = *(const float4*)(Kf + r * 64 + c4);
                float4 vv = *(const float4*)(Vf + r * 64 + c4);
                uint32_t kh01 = pack_hi(kv.x, kv.y), kh23 = pack_hi(kv.z, kv.w);
                *(uint32_t*)(Kh + r * PITCH + c4)     = kh01;
                *(uint32_t*)(Kh + r * PITCH + c4 + 2) = kh23;
                *(uint32_t*)(Kl + r * PITCH + c4)     = pack_res(kv.x, kv.y, kh01);
                *(uint32_t*)(Kl + r * PITCH + c4 + 2) = pack_res(kv.z, kv.w, kh23);
                uint32_t vh01 = pack_hi(vv.x, vv.y), vh23 = pack_hi(vv.z, vv.w);
                *(uint32_t*)(Vh + r * PITCH + c4)     = vh01;
                *(uint32_t*)(Vh + r * PITCH + c4 + 2) = vh23;
                *(uint32_t*)(Vl + r * PITCH + c4)     = pack_res(vv.x, vv.y, vh01);
                *(uint32_t*)(Vl + r * PITCH + c4 + 2) = pack_res(vv.z, vv.w, vh23);
            }
        }
        __syncthreads();
        if (kt < kt_max) issue_kv(kt + 1, p ^ 1);   // overlap with compute below
        if (k0 > wrow_max) continue;

        // ---- S = Q K^T (3 split terms) ----
        float S[8][4] = {};
        {
            int krow = (lane & 7);
            int kcol8 = 8 * ((lane >> 3) & 1);
            #pragma unroll
            for (int nb = 0; nb < 8; nb++) {
                #pragma unroll
                for (int ks = 0; ks < 4; ks++) {
                    uint32_t bh0, bh1, bl0, bl1;
                    LDSM_X2(bh0, bh1, smem_u32(Kh + (nb * 8 + krow) * PITCH + ks * 16 + kcol8));
                    LDSM_X2(bl0, bl1, smem_u32(Kl + (nb * 8 + krow) * PITCH + ks * 16 + kcol8));
                    MMA16816(S[nb], qh[ks], bh0, bh1);
                    MMA16816(S[nb], ql[ks], bh0, bh1);
                    MMA16816(S[nb], qh[ks], bl0, bl1);
                }
            }
        }

        // ---- mask + online softmax ----
        float ml0 = -1e30f, ml1 = -1e30f;
        #pragma unroll
        for (int nb = 0; nb < 8; nb++) {
            int c0 = k0 + nb * 8 + cb;
            S[nb][0] = (c0     <= row0 && c0     < len) ? S[nb][0] * 0.125f : -1e30f;
            S[nb][1] = (c0 + 1 <= row0 && c0 + 1 < len) ? S[nb][1] * 0.125f : -1e30f;
            S[nb][2] = (c0     <= row1 && c0     < len) ? S[nb][2] * 0.125f : -1e30f;
            S[nb][3] = (c0 + 1 <= row1 && c0 + 1 < len) ? S[nb][3] * 0.125f : -1e30f;
            ml0 = fmaxf(ml0, fmaxf(S[nb][0], S[nb][1]));
            ml1 = fmaxf(ml1, fmaxf(S[nb][2], S[nb][3]));
        }
        ml0 = fmaxf(ml0, __shfl_xor_sync(0xffffffffu, ml0, 1));
        ml0 = fmaxf(ml0, __shfl_xor_sync(0xffffffffu, ml0, 2));
        ml1 = fmaxf(ml1, __shfl_xor_sync(0xffffffffu, ml1, 1));
        ml1 = fmaxf(ml1, __shfl_xor_sync(0xffffffffu, ml1, 2));
        float mn0 = fmaxf(m_[0], ml0), mn1 = fmaxf(m_[1], ml1);
        float corr0 = __expf(m_[0] - mn0), corr1 = __expf(m_[1] - mn1);
        float ls0 = 0.f, ls1 = 0.f;
        #pragma unroll
        for (int nb = 0; nb < 8; nb++) {
            S[nb][0] = __expf(S[nb][0] - mn0); ls0 += S[nb][0];
            S[nb][1] = __expf(S[nb][1] - mn0); ls0 += S[nb][1];
            S[nb][2] = __expf(S[nb][2] - mn1); ls1 += S[nb][2];
            S[nb][3] = __expf(S[nb][3] - mn1); ls1 += S[nb][3];
        }
        ls0 += __shfl_xor_sync(0xffffffffu, ls0, 1);
        ls0 += __shfl_xor_sync(0xffffffffu, ls0, 2);
        ls1 += __shfl_xor_sync(0xffffffffu, ls1, 1);
        ls1 += __shfl_xor_sync(0xffffffffu, ls1, 2);
        l_[0] = l_[0] * corr0 + ls0;
        l_[1] = l_[1] * corr1 + ls1;
        m_[0] = mn0; m_[1] = mn1;
        #pragma unroll
        for (int nb = 0; nb < 8; nb++) {
            O[nb][0] *= corr0; O[nb][1] *= corr0;
            O[nb][2] *= corr1; O[nb][3] *= corr1;
        }

        // ---- O += P V (3 split terms) ----
        {
            int vrow8 = (lane & 7) + 8 * ((lane >> 3) & 1);
            #pragma unroll
            for (int ks = 0; ks < 4; ks++) {
                uint32_t ph[4], pl[4];
                ph[0] = pack_hi(S[2 * ks][0], S[2 * ks][1]);
                ph[1] = pack_hi(S[2 * ks][2], S[2 * ks][3]);
                ph[2] = pack_hi(S[2 * ks + 1][0], S[2 * ks + 1][1]);
                ph[3] = pack_hi(S[2 * ks + 1][2], S[2 * ks + 1][3]);
                pl[0] = pack_res(S[2 * ks][0], S[2 * ks][1], ph[0]);
                pl[1] = pack_res(S[2 * ks][2], S[2 * ks][3], ph[1]);
                pl[2] = pack_res(S[2 * ks + 1][0], S[2 * ks + 1][1], ph[2]);
                pl[3] = pack_res(S[2 * ks + 1][2], S[2 * ks + 1][3], ph[3]);
                #pragma unroll
                for (int nb = 0; nb < 8; nb++) {
                    uint32_t vh0, vh1, vl0, vl1;
                    LDSM_X2T(vh0, vh1, smem_u32(Vh + (ks * 16 + vrow8) * PITCH + nb * 8));
                    LDSM_X2T(vl0, vl1, smem_u32(Vl + (ks * 16 + vrow8) * PITCH + nb * 8));
                    MMA16816(O[nb], ph, vh0, vh1);
                    MMA16816(O[nb], pl, vh0, vh1);
                    MMA16816(O[nb], ph, vl0, vl1);
                }
            }
        }
    }

    // ---- epilogue: normalize, split hi/lo, store ----
    float inv0 = (row0 < len && l_[0] > 0.f) ? (1.f / l_[0]) : 0.f;
    float inv1 = (row1 < len && l_[1] > 0.f) ? (1.f / l_[1]) : 0.f;
    size_t rb0 = ((size_t)b * T_ + row0) * C_;
    size_t rb1 = ((size_t)b * T_ + row1) * C_;
    #pragma unroll
    for (int nb = 0; nb < 8; nb++) {
        int hcol = h * HD_ + nb * 8 + cb;
        uint32_t h0 = pack_hi(O[nb][0] * inv0, O[nb][1] * inv0);
        uint32_t l0 = pack_res(O[nb][0] * inv0, O[nb][1] * inv0, h0);
        uint32_t h1 = pack_hi(O[nb][2] * inv1, O[nb][3] * inv1);
        uint32_t l1 = pack_res(O[nb][2] * inv1, O[nb][3] * inv1, h1);
        *(uint32_t*)(yh + rb0 + hcol) = h0;
        *(uint32_t*)(yl + rb0 + hcol) = l0;
        *(uint32_t*)(yh + rb1 + hcol) = h1;
        *(uint32_t*)(yl + rb1 + hcol) = l1;
    }
}

// ---------------------------------------------------------------------------
extern "C" void kernel_launch(void* const* d_in, const int* in_sizes, int n_in,
                              void* d_out, int out_size)
{
    const float* x    = (const float*)d_in[0];
    const int*   am   = (const int*)  d_in[1];
    const float* Wqkv = (const float*)d_in[2];
    const float* bqkv = (const float*)d_in[3];
    const float* Wo   = (const float*)d_in[4];
    const float* bo   = (const float*)d_in[5];
    float* out = (float*)d_out;

    float* qkv;
    __nv_bfloat16 *xh, *xl, *wqh, *wql, *woh, *wol, *yh, *yl;
    int* lenp;
    cudaGetSymbolAddress((void**)&qkv, g_qkv);
    cudaGetSymbolAddress((void**)&xh, g_xh);   cudaGetSymbolAddress((void**)&xl, g_xl);
    cudaGetSymbolAddress((void**)&wqh, g_wqh); cudaGetSymbolAddress((void**)&wql, g_wql);
    cudaGetSymbolAddress((void**)&woh, g_woh); cudaGetSymbolAddress((void**)&wol, g_wol);
    cudaGetSymbolAddress((void**)&yh, g_yh);   cudaGetSymbolAddress((void**)&yl, g_yl);
    cudaGetSymbolAddress((void**)&lenp, g_len);

    cudaFuncSetAttribute(gemm_bf16, cudaFuncAttributeMaxDynamicSharedMemorySize, GEMM_SMEM);
    cudaFuncSetAttribute(flash_attn_tc, cudaFuncAttributeMaxDynamicSharedMemorySize, ATTN_SMEM);

    int nx = M_ * C_, nwq = C3_ * C_, nwo = C_ * C_;
    compute_len<<<B_, 256>>>(am, lenp);
    split_hl<<<nx  / 1024, 256>>>(x,    xh,  xl,  nx);
    split_hl<<<nwq / 1024, 256>>>(Wqkv, wqh, wql, nwq);
    split_hl<<<nwo / 1024, 256>>>(Wo,   woh, wol, nwo);

    gemm_bf16<<<dim3(C3_ / 128, M_ / 128), 256, GEMM_SMEM>>>(
        xh, xl, wqh, wql, bqkv, qkv, M_, C3_, C_);
    flash_attn_tc<<<dim3(T_ / 128, H_, B_), 256, ATTN_SMEM>>>(qkv, lenp, yh, yl);
    gemm_bf16<<<dim3(C_ / 128, M_ / 128), 256, GEMM_SMEM>>>(
        yh, yl, woh, wol, bo, out, M_, C_, C_);
}